// round 4
// baseline (speedup 1.0000x reference)
#include <cuda_runtime.h>
#include <math.h>

#define T_  256
#define B_  64
#define IN_ 512
#define H_  512

// ---------------- scratch (device globals; no allocation allowed) ----------------
__device__ float g_gx [(size_t)T_ * 8 * B_ * H_];   // [t][d*4+g][b][h]  (256 MB, reused per layer)
__device__ float g_hs0[(size_t)T_ * B_ * 2 * H_];   // layer-0 output [t][b][d*H+h] (64 MB)
__device__ float g_h  [2][2 * B_ * H_];             // [layer][d][b][h]
__device__ float g_c  [2][2 * B_ * H_];
__device__ float g_hn [2][2 * 4 * B_ * H_];         // ping-pong [buf][d][g][b][h] = h * noise_hid

// ---------------- init: zero states + hn buffer 0 ----------------
__global__ void init_kernel(int layer) {
    int i = blockIdx.x * blockDim.x + threadIdx.x;   // 262144 threads
    if (i < 2 * B_ * H_) { g_h[layer][i] = 0.f; g_c[layer][i] = 0.f; }
    if (i < 8 * B_ * H_) g_hn[0][i] = 0.f;
}

// ---------------- gx GEMM: gx[t][dg][b][h] = sum_i X[t][b][i]*noise[dg][b][i]*W[dg][i][h] + bias[dg][h]
// grid: (H/64, T, 8), block 16x16, each thread 4x4, BK=16
__global__ __launch_bounds__(256) void gx_kernel(
    const float* __restrict__ X,      // [T][B][K] (nullptr for layer1 -> g_hs0)
    const float* __restrict__ noise,  // [2][4][B][K]
    const float* __restrict__ W,      // [2][4][K][H]
    const float* __restrict__ bias,   // [2][4][H]
    int K, int layer)
{
    const int t  = blockIdx.y;
    const int dg = blockIdx.z;
    const int n0 = blockIdx.x * 64;
    const int tx = threadIdx.x, ty = threadIdx.y;
    const int tid = ty * 16 + tx;

    __shared__ __align__(16) float As[16][64];   // [k][m]
    __shared__ __align__(16) float Bs[16][64];   // [k][n]

    const float* Xsrc = layer ? g_hs0 : X;
    const float* Xt = Xsrc + (size_t)t * B_ * K;
    const float* Nz = noise + (size_t)dg * B_ * K;
    const float* Wg = W + (size_t)dg * K * H_;

    const int am = tid >> 2;          // 0..63  (row = b)
    const int ak = (tid & 3) * 4;     // 0,4,8,12
    const int bk = tid >> 4;          // 0..15
    const int bn = (tid & 15) * 4;

    float acc[4][4] = {};

    for (int k0 = 0; k0 < K; k0 += 16) {
        float4 xv = *(const float4*)(Xt + (size_t)am * K + k0 + ak);
        float4 nv = *(const float4*)(Nz + (size_t)am * K + k0 + ak);
        As[ak + 0][am] = xv.x * nv.x;
        As[ak + 1][am] = xv.y * nv.y;
        As[ak + 2][am] = xv.z * nv.z;
        As[ak + 3][am] = xv.w * nv.w;
        *(float4*)&Bs[bk][bn] = *(const float4*)(Wg + (size_t)(k0 + bk) * H_ + n0 + bn);
        __syncthreads();
#pragma unroll
        for (int kk = 0; kk < 16; kk++) {
            float4 a = *(const float4*)&As[kk][ty * 4];
            float4 b = *(const float4*)&Bs[kk][tx * 4];
            acc[0][0] += a.x * b.x; acc[0][1] += a.x * b.y; acc[0][2] += a.x * b.z; acc[0][3] += a.x * b.w;
            acc[1][0] += a.y * b.x; acc[1][1] += a.y * b.y; acc[1][2] += a.y * b.z; acc[1][3] += a.y * b.w;
            acc[2][0] += a.z * b.x; acc[2][1] += a.z * b.y; acc[2][2] += a.z * b.z; acc[2][3] += a.z * b.w;
            acc[3][0] += a.w * b.x; acc[3][1] += a.w * b.y; acc[3][2] += a.w * b.z; acc[3][3] += a.w * b.w;
        }
        __syncthreads();
    }

    float* out = g_gx + (((size_t)t * 8 + dg) * B_) * H_;
#pragma unroll
    for (int i = 0; i < 4; i++) {
        int m = ty * 4 + i;
        int n = n0 + tx * 4;
        float4 bv = *(const float4*)(bias + (size_t)dg * H_ + n);
        float4 o;
        o.x = acc[i][0] + bv.x; o.y = acc[i][1] + bv.y;
        o.z = acc[i][2] + bv.z; o.w = acc[i][3] + bv.w;
        *(float4*)(out + (size_t)m * H_ + n) = o;
    }
}

// ---------------- step kernel: both directions of one layer, one timestep
// grid: (H/16=32, B/32=2, d=2), 128 threads: g = tid>>5, within gate 8x4 threads of 4b x 4h
__global__ __launch_bounds__(128) void step_kernel(
    const float* __restrict__ w_hh,       // [2][4][H][H]
    const float* __restrict__ b_hh,       // [2][4][H]
    const float* __restrict__ noise_hid,  // [2][4][B][H]
    const float* __restrict__ mask,       // [T][B]
    int layer, int s, float* __restrict__ out)
{
    const int d  = blockIdx.z;
    const int b0 = blockIdx.y * 32;
    const int h0 = blockIdx.x * 16;
    const int t  = d ? (T_ - 1 - s) : s;
    const int tid  = threadIdx.x;
    const int g    = tid >> 5;
    const int lane = tid & 31;
    const int bq = lane >> 2;     // 0..7
    const int hq = lane & 3;      // 0..3

    __shared__ __align__(16) float hnS[4][32][33];   // [g][jj][b] (padded)
    __shared__ __align__(16) float wS [4][32][20];   // [g][jj][h] (padded)

    const float* hn_in  = g_hn[s & 1]       + (size_t)d * 4 * B_ * H_;
    float*       hn_out = g_hn[(s + 1) & 1];
    float* hst = g_h[layer];
    float* cst = g_c[layer];
    float* out_hs = layer ? out : g_hs0;
    const float* wD = w_hh + (size_t)d * 4 * H_ * H_;

    float acc[4][4] = {};

    for (int j0 = 0; j0 < H_; j0 += 32) {
        // hn tile -> transposed smem
#pragma unroll
        for (int i = 0; i < 8; i++) {
            int idx = tid + i * 128;               // float4 index over 4096 floats
            int jj4 = idx & 7;
            int bb  = (idx >> 3) & 31;
            int gg  = idx >> 8;
            float4 v = *(const float4*)(hn_in + ((size_t)gg * B_ + b0 + bb) * H_ + j0 + jj4 * 4);
            hnS[gg][jj4 * 4 + 0][bb] = v.x;
            hnS[gg][jj4 * 4 + 1][bb] = v.y;
            hnS[gg][jj4 * 4 + 2][bb] = v.z;
            hnS[gg][jj4 * 4 + 3][bb] = v.w;
        }
        // w tile
#pragma unroll
        for (int i = 0; i < 4; i++) {
            int idx = tid + i * 128;               // float4 index over 2048 floats
            int hh4 = idx & 3;
            int jj  = (idx >> 2) & 31;
            int gg  = idx >> 7;
            float4 v = *(const float4*)(wD + ((size_t)gg * H_ + j0 + jj) * H_ + h0 + hh4 * 4);
            *(float4*)&wS[gg][jj][hh4 * 4] = v;
        }
        __syncthreads();
#pragma unroll
        for (int jj = 0; jj < 32; jj++) {
            float a0 = hnS[g][jj][bq * 4 + 0];
            float a1 = hnS[g][jj][bq * 4 + 1];
            float a2 = hnS[g][jj][bq * 4 + 2];
            float a3 = hnS[g][jj][bq * 4 + 3];
            float4 w4 = *(const float4*)&wS[g][jj][hq * 4];
            acc[0][0] += a0 * w4.x; acc[0][1] += a0 * w4.y; acc[0][2] += a0 * w4.z; acc[0][3] += a0 * w4.w;
            acc[1][0] += a1 * w4.x; acc[1][1] += a1 * w4.y; acc[1][2] += a1 * w4.z; acc[1][3] += a1 * w4.w;
            acc[2][0] += a2 * w4.x; acc[2][1] += a2 * w4.y; acc[2][2] += a2 * w4.z; acc[2][3] += a2 * w4.w;
            acc[3][0] += a3 * w4.x; acc[3][1] += a3 * w4.y; acc[3][2] += a3 * w4.z; acc[3][3] += a3 * w4.w;
        }
        __syncthreads();
    }

    // exchange gate partials through smem (reuse hnS region): gS[g][b(32)][h(16)]
    float* gS = &hnS[0][0][0];
#pragma unroll
    for (int i = 0; i < 4; i++)
#pragma unroll
        for (int j = 0; j < 4; j++)
            gS[((size_t)g * 32 + bq * 4 + i) * 16 + hq * 4 + j] = acc[i][j];
    __syncthreads();

    // fused LSTM pointwise + mask blend + next-step hn production
#pragma unroll
    for (int i = 0; i < 4; i++) {
        int e  = tid + i * 128;      // 0..511
        int bb = e >> 4, hh = e & 15;
        int bg = b0 + bb, hg = h0 + hh;
        const float* bh = b_hh + (size_t)d * 4 * H_;
        size_t gxb = (((size_t)t * 8 + d * 4) * B_ + bg) * H_ + hg;
        float xi = gS[(0 * 32 + bb) * 16 + hh] + g_gx[gxb            ] + bh[0 * H_ + hg];
        float xf = gS[(1 * 32 + bb) * 16 + hh] + g_gx[gxb + 1 * 32768] + bh[1 * H_ + hg];
        float xg = gS[(2 * 32 + bb) * 16 + hh] + g_gx[gxb + 2 * 32768] + bh[2 * H_ + hg];
        float xo = gS[(3 * 32 + bb) * 16 + hh] + g_gx[gxb + 3 * 32768] + bh[3 * H_ + hg];

        float ig = 1.f / (1.f + expf(-xi));
        float fg = 1.f / (1.f + expf(-xf));
        float gt = tanhf(xg);
        float og = 1.f / (1.f + expf(-xo));

        size_t sidx = ((size_t)d * B_ + bg) * H_ + hg;
        float hp = hst[sidx], cp = cst[sidx];
        float cn = fg * cp + ig * gt;
        float hv = og * tanhf(cn);
        float mt = mask[(size_t)t * B_ + bg];
        float hb = hv * mt + hp * (1.f - mt);
        float cb = cn * mt + cp * (1.f - mt);
        hst[sidx] = hb;
        cst[sidx] = cb;
#pragma unroll
        for (int gg = 0; gg < 4; gg++) {
            size_t nidx = (((size_t)d * 4 + gg) * B_ + bg) * H_ + hg;
            hn_out[nidx] = hb * noise_hid[nidx];
        }
        out_hs[((size_t)t * B_ + bg) * (2 * H_) + (size_t)d * H_ + hg] = hb;
    }
}

// ---------------- finalize: h_n / c_n ----------------
__global__ void final_kernel(float* __restrict__ out) {
    int i = blockIdx.x * blockDim.x + threadIdx.x;   // 131072
    if (i >= 4 * B_ * H_) return;
    int l = i >> 16;          // 65536 elements per layer (2 dirs)
    int r = i & 65535;
    size_t O = (size_t)T_ * B_ * 2 * H_;
    out[O + i]          = g_h[l][r];
    out[O + 131072 + i] = g_c[l][r];
}

// ---------------- launch ----------------
extern "C" void kernel_launch(void* const* d_in, const int* in_sizes, int n_in,
                              void* d_out, int out_size) {
    const float* x            = (const float*)d_in[0];
    const float* mask         = (const float*)d_in[1];
    const float* w_ih_l0      = (const float*)d_in[2];
    const float* w_hh_l0      = (const float*)d_in[3];
    const float* b_ih_l0      = (const float*)d_in[4];
    const float* b_hh_l0      = (const float*)d_in[5];
    const float* noise_in_l0  = (const float*)d_in[6];
    const float* noise_hid_l0 = (const float*)d_in[7];
    const float* w_ih_l1      = (const float*)d_in[8];
    const float* w_hh_l1      = (const float*)d_in[9];
    const float* b_ih_l1      = (const float*)d_in[10];
    const float* b_hh_l1      = (const float*)d_in[11];
    const float* noise_in_l1  = (const float*)d_in[12];
    const float* noise_hid_l1 = (const float*)d_in[13];
    float* out = (float*)d_out;

    dim3 gxGrid(H_ / 64, T_, 8), gxBlock(16, 16);
    dim3 stGrid(H_ / 16, B_ / 32, 2);

    // ----- layer 0 -----
    init_kernel<<<512, 512>>>(0);
    gx_kernel<<<gxGrid, gxBlock>>>(x, noise_in_l0, w_ih_l0, b_ih_l0, IN_, 0);
    for (int s = 0; s < T_; s++)
        step_kernel<<<stGrid, 128>>>(w_hh_l0, b_hh_l0, noise_hid_l0, mask, 0, s, out);

    // ----- layer 1 -----
    init_kernel<<<512, 512>>>(1);
    gx_kernel<<<gxGrid, gxBlock>>>(nullptr, noise_in_l1, w_ih_l1, b_ih_l1, 2 * H_, 1);
    for (int s = 0; s < T_; s++)
        step_kernel<<<stGrid, 128>>>(w_hh_l1, b_hh_l1, noise_hid_l1, mask, 1, s, out);

    final_kernel<<<256, 512>>>(out);
}

// round 5
// speedup vs baseline: 1.1469x; 1.1469x over previous
#include <cuda_runtime.h>
#include <math.h>

#define T_  256
#define B_  64
#define IN_ 512
#define H_  512
#define NBLK 128
#define JC   64
#define NCHUNK (H_ / JC)          // 8
#define HNBUF (4 * JC * B_)       // 16384 floats per chunk buffer

// ---------------- scratch (device globals; no allocation allowed) ----------------
__device__ float g_gx [(size_t)T_ * 8 * H_ * B_];   // [t][dg][h][b]  (transposed!)
__device__ float g_hs0[(size_t)T_ * B_ * 2 * H_];   // layer-0 output [t][b][d*H+h]
__device__ float g_h  [2][2 * B_ * H_];             // [layer][d][b][h]
__device__ float g_c  [2][2 * B_ * H_];
__device__ float g_hn [2][8 * H_ * B_];             // ping-pong [buf][d*4+g][h][b]
__device__ unsigned g_bar_cnt;
__device__ volatile unsigned g_bar_gen;

// ---------------- cp.async helpers ----------------
__device__ __forceinline__ void cp_async16(float* dst_smem, const float* src) {
    unsigned s = (unsigned)__cvta_generic_to_shared(dst_smem);
    asm volatile("cp.async.cg.shared.global [%0], [%1], 16;\n" :: "r"(s), "l"(src));
}
#define CP_COMMIT()  asm volatile("cp.async.commit_group;\n" ::: "memory")
#define CP_WAIT1()   asm volatile("cp.async.wait_group 1;\n" ::: "memory")
#define CP_WAIT0()   asm volatile("cp.async.wait_group 0;\n" ::: "memory")

// ---------------- init ----------------
__global__ void init_kernel(int layer) {
    int i = blockIdx.x * blockDim.x + threadIdx.x;   // 262144 threads
    if (i < 2 * B_ * H_) { g_h[layer][i] = 0.f; g_c[layer][i] = 0.f; }
    if (i < 8 * H_ * B_) g_hn[0][i] = 0.f;
    if (i == 0) { g_bar_cnt = 0; g_bar_gen = 0; }
}

// ---------------- gx GEMM (output transposed to [t][dg][h][b]) ----------------
__global__ __launch_bounds__(256) void gx_kernel(
    const float* __restrict__ X,
    const float* __restrict__ noise,
    const float* __restrict__ W,
    const float* __restrict__ bias,
    int K, int layer)
{
    const int t  = blockIdx.y;
    const int dg = blockIdx.z;
    const int n0 = blockIdx.x * 64;
    const int tx = threadIdx.x, ty = threadIdx.y;
    const int tid = ty * 16 + tx;

    __shared__ __align__(16) float As[16][64];
    __shared__ __align__(16) float Bs[16][64];

    const float* Xsrc = layer ? g_hs0 : X;
    const float* Xt = Xsrc + (size_t)t * B_ * K;
    const float* Nz = noise + (size_t)dg * B_ * K;
    const float* Wg = W + (size_t)dg * K * H_;

    const int am = tid >> 2;
    const int ak = (tid & 3) * 4;
    const int bk = tid >> 4;
    const int bn = (tid & 15) * 4;

    float acc[4][4] = {};

    for (int k0 = 0; k0 < K; k0 += 16) {
        float4 xv = *(const float4*)(Xt + (size_t)am * K + k0 + ak);
        float4 nv = *(const float4*)(Nz + (size_t)am * K + k0 + ak);
        As[ak + 0][am] = xv.x * nv.x;
        As[ak + 1][am] = xv.y * nv.y;
        As[ak + 2][am] = xv.z * nv.z;
        As[ak + 3][am] = xv.w * nv.w;
        *(float4*)&Bs[bk][bn] = *(const float4*)(Wg + (size_t)(k0 + bk) * H_ + n0 + bn);
        __syncthreads();
#pragma unroll
        for (int kk = 0; kk < 16; kk++) {
            float4 a = *(const float4*)&As[kk][ty * 4];
            float4 b = *(const float4*)&Bs[kk][tx * 4];
            acc[0][0] += a.x * b.x; acc[0][1] += a.x * b.y; acc[0][2] += a.x * b.z; acc[0][3] += a.x * b.w;
            acc[1][0] += a.y * b.x; acc[1][1] += a.y * b.y; acc[1][2] += a.y * b.z; acc[1][3] += a.y * b.w;
            acc[2][0] += a.z * b.x; acc[2][1] += a.z * b.y; acc[2][2] += a.z * b.z; acc[2][3] += a.z * b.w;
            acc[3][0] += a.w * b.x; acc[3][1] += a.w * b.y; acc[3][2] += a.w * b.z; acc[3][3] += a.w * b.w;
        }
        __syncthreads();
    }

    // transposed store: g_gx[t][dg][h][b]
    float* outb = g_gx + ((size_t)t * 8 + dg) * H_ * B_;
    float4 bv = *(const float4*)(bias + (size_t)dg * H_ + n0 + tx * 4);
#pragma unroll
    for (int i = 0; i < 4; i++) {
        int m = ty * 4 + i;             // b
        int n = n0 + tx * 4;            // h
        outb[(size_t)(n + 0) * B_ + m] = acc[i][0] + bv.x;
        outb[(size_t)(n + 1) * B_ + m] = acc[i][1] + bv.y;
        outb[(size_t)(n + 2) * B_ + m] = acc[i][2] + bv.z;
        outb[(size_t)(n + 3) * B_ + m] = acc[i][3] + bv.w;
    }
}

// ---------------- persistent scan: one launch does all 256 steps of a layer ----------------
// grid 128 = d(2) x htile(64, 8h each); 512 threads; weights resident in smem.
__global__ __launch_bounds__(512, 1) void scan_kernel(
    const float* __restrict__ w_hh,       // [2][4][H][H]
    const float* __restrict__ b_hh,       // [2][4][H]
    const float* __restrict__ noise_hid,  // [2][4][B][H]
    const float* __restrict__ mask,       // [T][B]
    int layer, float* __restrict__ out)
{
    extern __shared__ __align__(16) float sm[];
    float* wS   = sm;                       // [4][512][8]   = 16384 floats
    float* hnS  = sm + 16384;               // [2][4][JC][64]= 32768 floats
    float* gBuf = sm + 16384 + 2 * HNBUF;   // [4][8][64]    = 2048 floats (reused as oBuf)

    const int tid = threadIdx.x;
    const int d   = blockIdx.x >> 6;
    const int h0  = (blockIdx.x & 63) * 8;

    // ---- load weight slice once: w_hh[d][g][j][h0..h0+7] ----
    for (int i = tid; i < 4096; i += 512) {       // 4096 float4s
        int g = i >> 10, rem = i & 1023;
        int j = rem >> 1, half = rem & 1;
        float4 v = *(const float4*)(w_hh + (((size_t)(d * 4 + g) * H_ + j) * H_ + h0 + half * 4));
        *(float4*)&wS[(g * 512 + j) * 8 + half * 4] = v;
    }

    // GEMM-side thread mapping
    const int gq  = tid >> 7;            // gate 0..3
    const int rr  = tid & 127;
    const int hlg = rr >> 4;             // 0..7
    const int bq  = (rr & 15) * 4;       // 0,4,..,60

    // pointwise-side thread mapping
    const int hl = tid >> 6;             // 0..7
    const int b  = tid & 63;

    // per-thread constants (pointwise side)
    float bh[4], nz[4];
#pragma unroll
    for (int g = 0; g < 4; g++) {
        bh[g] = b_hh[(size_t)(d * 4 + g) * H_ + h0 + hl];
        nz[g] = noise_hid[((size_t)(d * 4 + g) * B_ + b) * H_ + h0 + hl];
    }
    float hreg = 0.f, creg = 0.f;
    float* outp = layer ? out : g_hs0;

    __syncthreads();

    for (int s = 0; s < T_; s++) {
        const int t = d ? (T_ - 1 - s) : s;
        const float* hn_in  = g_hn[s & 1];
        float*       hn_out = g_hn[(s + 1) & 1];

        // ---------- GEMM over K=512 in chunks of JC, cp.async double-buffered ----------
        float acc0 = 0.f, acc1 = 0.f, acc2 = 0.f, acc3 = 0.f;

        // prefetch chunk 0
#pragma unroll
        for (int k = 0; k < 8; k++) {
            int i = tid + k * 512;
            int g = i >> 10, jj = (i >> 4) & 63, b4 = (i & 15) * 4;
            cp_async16(&hnS[(g * JC + jj) * B_ + b4],
                       hn_in + (((size_t)(d * 4 + g) * H_) + jj) * B_ + b4);
        }
        CP_COMMIT();

        for (int c = 0; c < NCHUNK; c++) {
            if (c + 1 < NCHUNK) {
                float* buf = hnS + ((c + 1) & 1) * HNBUF;
#pragma unroll
                for (int k = 0; k < 8; k++) {
                    int i = tid + k * 512;
                    int g = i >> 10, jj = (i >> 4) & 63, b4 = (i & 15) * 4;
                    cp_async16(&buf[(g * JC + jj) * B_ + b4],
                               hn_in + (((size_t)(d * 4 + g) * H_) + (c + 1) * JC + jj) * B_ + b4);
                }
                CP_COMMIT();
                CP_WAIT1();
            } else {
                CP_WAIT0();
            }
            __syncthreads();

            const float* hb = hnS + (c & 1) * HNBUF + gq * (JC * B_);
            const float* wr = wS + (gq * 512 + c * JC) * 8 + hlg;
#pragma unroll 8
            for (int jj = 0; jj < JC; jj++) {
                float4 a = *(const float4*)(hb + jj * B_ + bq);
                float  w = wr[jj * 8];
                acc0 += a.x * w; acc1 += a.y * w; acc2 += a.z * w; acc3 += a.w * w;
            }
            __syncthreads();
        }

        // ---------- gate exchange ----------
        gBuf[(gq * 8 + hlg) * B_ + bq + 0] = acc0;
        gBuf[(gq * 8 + hlg) * B_ + bq + 1] = acc1;
        gBuf[(gq * 8 + hlg) * B_ + bq + 2] = acc2;
        gBuf[(gq * 8 + hlg) * B_ + bq + 3] = acc3;
        __syncthreads();

        // ---------- LSTM pointwise (thread owns (b, h0+hl) of direction d) ----------
        const size_t gxbase = ((size_t)t * 8 + d * 4) * (H_ * B_) + (size_t)(h0 + hl) * B_ + b;
        float x0 = gBuf[(0 * 8 + hl) * B_ + b] + g_gx[gxbase + 0 * (H_ * B_)] + bh[0];
        float x1 = gBuf[(1 * 8 + hl) * B_ + b] + g_gx[gxbase + 1 * (H_ * B_)] + bh[1];
        float x2 = gBuf[(2 * 8 + hl) * B_ + b] + g_gx[gxbase + 2 * (H_ * B_)] + bh[2];
        float x3 = gBuf[(3 * 8 + hl) * B_ + b] + g_gx[gxbase + 3 * (H_ * B_)] + bh[3];

        float ig = 1.f / (1.f + __expf(-x0));
        float fg = 1.f / (1.f + __expf(-x1));
        float gt = tanhf(x2);
        float og = 1.f / (1.f + __expf(-x3));

        float cn = fg * creg + ig * gt;
        float hv = og * tanhf(cn);
        float mt = mask[(size_t)t * B_ + b];
        hreg = hv * mt + hreg * (1.f - mt);
        creg = cn * mt + creg * (1.f - mt);

        // next-step hn (coalesced: b contiguous)
        const size_t nb = ((size_t)(d * 4) * H_ + h0 + hl) * B_ + b;
        hn_out[nb + 0 * (H_ * B_)] = hreg * nz[0];
        hn_out[nb + 1 * (H_ * B_)] = hreg * nz[1];
        hn_out[nb + 2 * (H_ * B_)] = hreg * nz[2];
        hn_out[nb + 3 * (H_ * B_)] = hreg * nz[3];

        // ---------- staged, vectorized output write ----------
        __syncthreads();                 // everyone done reading gBuf as gates
        gBuf[b * 8 + hl] = hreg;         // reuse as oBuf [b][8h]
        __syncthreads();
        if (tid < 128) {
            int bb = tid >> 1, q = tid & 1;
            float4 v = *(const float4*)&gBuf[bb * 8 + q * 4];
            *(float4*)(outp + ((size_t)t * B_ + bb) * (2 * H_) + (size_t)d * H_ + h0 + q * 4) = v;
        }

        if (s == T_ - 1) {
            g_h[layer][((size_t)d * B_ + b) * H_ + h0 + hl] = hreg;
            g_c[layer][((size_t)d * B_ + b) * H_ + h0 + hl] = creg;
        }

        // ---------- grid barrier ----------
        __threadfence();
        __syncthreads();
        if (tid == 0) {
            unsigned a = atomicAdd(&g_bar_cnt, 1u);
            if (a == (unsigned)(NBLK * (s + 1)) - 1u) {
                g_bar_gen = (unsigned)(s + 1);
            } else {
                while (g_bar_gen < (unsigned)(s + 1)) { }
            }
            __threadfence();
        }
        __syncthreads();
    }
}

// ---------------- finalize ----------------
__global__ void final_kernel(float* __restrict__ out) {
    int i = blockIdx.x * blockDim.x + threadIdx.x;
    if (i >= 4 * B_ * H_) return;
    int l = i >> 16;
    int r = i & 65535;
    size_t O = (size_t)T_ * B_ * 2 * H_;
    out[O + i]          = g_h[l][r];
    out[O + 131072 + i] = g_c[l][r];
}

// ---------------- launch ----------------
extern "C" void kernel_launch(void* const* d_in, const int* in_sizes, int n_in,
                              void* d_out, int out_size) {
    const float* x            = (const float*)d_in[0];
    const float* mask         = (const float*)d_in[1];
    const float* w_ih_l0      = (const float*)d_in[2];
    const float* w_hh_l0      = (const float*)d_in[3];
    const float* b_ih_l0      = (const float*)d_in[4];
    const float* b_hh_l0      = (const float*)d_in[5];
    const float* noise_in_l0  = (const float*)d_in[6];
    const float* noise_hid_l0 = (const float*)d_in[7];
    const float* w_ih_l1      = (const float*)d_in[8];
    const float* w_hh_l1      = (const float*)d_in[9];
    const float* b_ih_l1      = (const float*)d_in[10];
    const float* b_hh_l1      = (const float*)d_in[11];
    const float* noise_in_l1  = (const float*)d_in[12];
    const float* noise_hid_l1 = (const float*)d_in[13];
    float* out = (float*)d_out;

    const int SMEM = (16384 + 2 * HNBUF + 2048) * sizeof(float);   // 204800 B
    cudaFuncSetAttribute(scan_kernel, cudaFuncAttributeMaxDynamicSharedMemorySize, SMEM);

    dim3 gxGrid(H_ / 64, T_, 8), gxBlock(16, 16);

    // ----- layer 0 -----
    init_kernel<<<512, 512>>>(0);
    gx_kernel<<<gxGrid, gxBlock>>>(x, noise_in_l0, w_ih_l0, b_ih_l0, IN_, 0);
    scan_kernel<<<NBLK, 512, SMEM>>>(w_hh_l0, b_hh_l0, noise_hid_l0, mask, 0, out);

    // ----- layer 1 -----
    init_kernel<<<512, 512>>>(1);
    gx_kernel<<<gxGrid, gxBlock>>>(nullptr, noise_in_l1, w_ih_l1, b_ih_l1, 2 * H_, 1);
    scan_kernel<<<NBLK, 512, SMEM>>>(w_hh_l1, b_hh_l1, noise_hid_l1, mask, 1, out);

    final_kernel<<<256, 512>>>(out);
}

// round 6
// speedup vs baseline: 1.1580x; 1.0097x over previous
#include <cuda_runtime.h>
#include <math.h>

#define T_  256
#define B_  64
#define IN_ 512
#define H_  512
#define NBLK 128
#define JC   64
#define NCHUNK (H_ / JC)          // 8
#define HNBUF (4 * JC * B_)       // 16384 floats per chunk buffer

// ---------------- scratch (device globals; no allocation allowed) ----------------
__device__ float g_gx [(size_t)T_ * 8 * H_ * B_];   // [t][dg][h][b]  (transposed)
__device__ float g_hs0[(size_t)T_ * B_ * 2 * H_];   // layer-0 output [t][b][d*H+h]
__device__ float g_h  [2][2 * B_ * H_];
__device__ float g_c  [2][2 * B_ * H_];
__device__ float g_hn [2][8 * H_ * B_];             // ping-pong [buf][d*4+g][h][b]
__device__ unsigned g_bar_cnt;
__device__ volatile unsigned g_bar_gen;

// ---------------- helpers ----------------
__device__ __forceinline__ unsigned f2tf32(float x) {
    unsigned r; asm("cvt.rna.tf32.f32 %0, %1;" : "=r"(r) : "f"(x)); return r;
}
__device__ __forceinline__ void cp_async16(float* dst_smem, const float* src) {
    unsigned s = (unsigned)__cvta_generic_to_shared(dst_smem);
    asm volatile("cp.async.cg.shared.global [%0], [%1], 16;\n" :: "r"(s), "l"(src));
}
#define CP_COMMIT()  asm volatile("cp.async.commit_group;\n" ::: "memory")
#define CP_WAIT1()   asm volatile("cp.async.wait_group 1;\n" ::: "memory")
#define CP_WAIT0()   asm volatile("cp.async.wait_group 0;\n" ::: "memory")

#define MMA_TF32(c, a, b) asm volatile( \
    "mma.sync.aligned.m16n8k8.row.col.f32.tf32.tf32.f32 " \
    "{%0,%1,%2,%3}, {%4,%5,%6,%7}, {%8,%9}, {%0,%1,%2,%3};" \
    : "+f"((c)[0]), "+f"((c)[1]), "+f"((c)[2]), "+f"((c)[3]) \
    : "r"((a)[0]), "r"((a)[1]), "r"((a)[2]), "r"((a)[3]), \
      "r"((b)[0]), "r"((b)[1]))

// ---------------- init ----------------
__global__ void init_kernel(int layer) {
    int i = blockIdx.x * blockDim.x + threadIdx.x;
    if (i < 2 * B_ * H_) { g_h[layer][i] = 0.f; g_c[layer][i] = 0.f; }
    if (i < 8 * H_ * B_) g_hn[0][i] = 0.f;
    if (i == 0) { g_bar_cnt = 0; g_bar_gen = 0; }
}

// ---------------- gx GEMM via 3xTF32 tensor cores ----------------
// One GEMM per dg: C[16384, 512] = (X .* noise)[16384, K] @ W[K, 512]
// BM=128, BN=64, BK=16; 256 threads (8 warps, 4m x 2n, warp tile 32x32).
// Output stored transposed: g_gx[t][dg][h][b], bias added in epilogue.
#define AST 132
#define BST 68
__global__ __launch_bounds__(256) void gx_tf32_kernel(
    const float* __restrict__ X,
    const float* __restrict__ noise,
    const float* __restrict__ W,
    const float* __restrict__ bias,
    int K, int layer)
{
    extern __shared__ __align__(16) float sm[];
    float* smA = sm;               // [buf][plane][16*AST]  4*2112
    float* smB = sm + 4 * 16 * AST;// [buf][plane][16*BST]  4*1088
    float* Cs  = sm;               // reuse: [128][65]

    const int dg = blockIdx.z;
    const int n0 = blockIdx.x * 64;
    const int m0 = blockIdx.y * 128;
    const int tid = threadIdx.x;
    const int lane = tid & 31;
    const int warp = tid >> 5;
    const int wm = warp & 3;       // 4 m-tiles of 32
    const int wn = warp >> 2;      // 2 n-tiles of 32

    // A loading role: m_l 0..127, kq in {0,8}
    const int m_l = tid >> 1;
    const int kq  = (tid & 1) * 8;
    // B loading role: k_l 0..15, n4 = 4-float group
    const int k_l = tid >> 4;
    const int n4  = (tid & 15) * 4;

    const float* Xsrc = layer ? g_hs0 : X;
    const float* xrow = Xsrc + (size_t)(m0 + m_l) * K;
    const float* nrow = noise + ((size_t)dg * B_ + ((m0 + m_l) & 63)) * K;
    const float* Wg   = W + (size_t)dg * K * H_;

    unsigned ahi[8], alo[8], bhi[4], blo[4];
    float acc[2][4][4] = {};

    const int nchunks = K >> 4;

    // ---- register load of chunk c ----
    auto loadRegs = [&](int c) {
        int k0 = c * 16;
#pragma unroll
        for (int j = 0; j < 2; j++) {
            float4 xv = *(const float4*)(xrow + k0 + kq + j * 4);
            float4 nv = *(const float4*)(nrow + k0 + kq + j * 4);
            float p[4] = { xv.x * nv.x, xv.y * nv.y, xv.z * nv.z, xv.w * nv.w };
#pragma unroll
            for (int i = 0; i < 4; i++) {
                unsigned h = f2tf32(p[i]);
                ahi[j * 4 + i] = h;
                alo[j * 4 + i] = f2tf32(p[i] - __uint_as_float(h));
            }
        }
        float4 wv = *(const float4*)(Wg + (size_t)(k0 + k_l) * H_ + n0 + n4);
        float q[4] = { wv.x, wv.y, wv.z, wv.w };
#pragma unroll
        for (int i = 0; i < 4; i++) {
            unsigned h = f2tf32(q[i]);
            bhi[i] = h;
            blo[i] = f2tf32(q[i] - __uint_as_float(h));
        }
    };

    auto storeSmem = [&](int buf) {
        float* Ah = smA + buf * 2 * 16 * AST;
        float* Al = Ah + 16 * AST;
#pragma unroll
        for (int j = 0; j < 2; j++)
#pragma unroll
            for (int i = 0; i < 4; i++) {
                Ah[(kq + j * 4 + i) * AST + m_l] = __uint_as_float(ahi[j * 4 + i]);
                Al[(kq + j * 4 + i) * AST + m_l] = __uint_as_float(alo[j * 4 + i]);
            }
        float* Bh = smB + buf * 2 * 16 * BST;
        float* Bl = Bh + 16 * BST;
#pragma unroll
        for (int i = 0; i < 4; i++) {
            Bh[k_l * BST + n4 + i] = __uint_as_float(bhi[i]);
            Bl[k_l * BST + n4 + i] = __uint_as_float(blo[i]);
        }
    };

    auto compute = [&](int buf) {
        const float* Ah = smA + buf * 2 * 16 * AST;
        const float* Al = Ah + 16 * AST;
        const float* Bh = smB + buf * 2 * 16 * BST;
        const float* Bl = Bh + 16 * BST;
#pragma unroll
        for (int ks = 0; ks < 2; ks++) {
            const int kc = ks * 8 + (lane & 3);
            unsigned ah[2][4], al[2][4], bh[4][2], bl[4][2];
#pragma unroll
            for (int im = 0; im < 2; im++) {
                int mr = wm * 32 + im * 16 + (lane >> 2);
                ah[im][0] = __float_as_uint(Ah[kc * AST + mr]);
                ah[im][1] = __float_as_uint(Ah[kc * AST + mr + 8]);
                ah[im][2] = __float_as_uint(Ah[(kc + 4) * AST + mr]);
                ah[im][3] = __float_as_uint(Ah[(kc + 4) * AST + mr + 8]);
                al[im][0] = __float_as_uint(Al[kc * AST + mr]);
                al[im][1] = __float_as_uint(Al[kc * AST + mr + 8]);
                al[im][2] = __float_as_uint(Al[(kc + 4) * AST + mr]);
                al[im][3] = __float_as_uint(Al[(kc + 4) * AST + mr + 8]);
            }
#pragma unroll
            for (int jn = 0; jn < 4; jn++) {
                int nc = wn * 32 + jn * 8 + (lane >> 2);
                bh[jn][0] = __float_as_uint(Bh[kc * BST + nc]);
                bh[jn][1] = __float_as_uint(Bh[(kc + 4) * BST + nc]);
                bl[jn][0] = __float_as_uint(Bl[kc * BST + nc]);
                bl[jn][1] = __float_as_uint(Bl[(kc + 4) * BST + nc]);
            }
#pragma unroll
            for (int im = 0; im < 2; im++)
#pragma unroll
                for (int jn = 0; jn < 4; jn++) {
                    MMA_TF32(acc[im][jn], ah[im], bh[jn]);   // hi*hi
                    MMA_TF32(acc[im][jn], ah[im], bl[jn]);   // hi*lo
                    MMA_TF32(acc[im][jn], al[im], bh[jn]);   // lo*hi
                }
        }
    };

    loadRegs(0);
    storeSmem(0);
    __syncthreads();
    for (int c = 0; c < nchunks; c++) {
        int cur = c & 1;
        bool more = (c + 1 < nchunks);
        if (more) loadRegs(c + 1);
        compute(cur);
        if (more) { __syncthreads(); storeSmem(cur ^ 1); __syncthreads(); }
    }
    __syncthreads();   // before reusing smem as Cs

    // stage C into smem [m(128)][n(64)] stride 65
#pragma unroll
    for (int im = 0; im < 2; im++)
#pragma unroll
        for (int jn = 0; jn < 4; jn++) {
            int r = wm * 32 + im * 16 + (lane >> 2);
            int c2 = wn * 32 + jn * 8 + (lane & 3) * 2;
            Cs[r * 65 + c2]           = acc[im][jn][0];
            Cs[r * 65 + c2 + 1]       = acc[im][jn][1];
            Cs[(r + 8) * 65 + c2]     = acc[im][jn][2];
            Cs[(r + 8) * 65 + c2 + 1] = acc[im][jn][3];
        }
    __syncthreads();

    // transposed, bias-added, coalesced store: g_gx[t][dg][h][b]
    const int t0 = m0 >> 6;
#pragma unroll
    for (int it = 0; it < 32; it++) {
        int e = tid + it * 256;       // 0..8191
        int b  = e & 63;
        int n  = (e >> 6) & 63;
        int tt = e >> 12;
        float v = Cs[(tt * 64 + b) * 65 + n] + __ldg(bias + (size_t)dg * H_ + n0 + n);
        g_gx[(((size_t)(t0 + tt) * 8 + dg) * H_ + n0 + n) * B_ + b] = v;
    }
}

// ---------------- persistent scan (unchanged from R5) ----------------
__global__ __launch_bounds__(512, 1) void scan_kernel(
    const float* __restrict__ w_hh,
    const float* __restrict__ b_hh,
    const float* __restrict__ noise_hid,
    const float* __restrict__ mask,
    int layer, float* __restrict__ out)
{
    extern __shared__ __align__(16) float sm[];
    float* wS   = sm;                       // [4][512][8]
    float* hnS  = sm + 16384;               // [2][4][JC][64]
    float* gBuf = sm + 16384 + 2 * HNBUF;   // [4][8][64]

    const int tid = threadIdx.x;
    const int d   = blockIdx.x >> 6;
    const int h0  = (blockIdx.x & 63) * 8;

    for (int i = tid; i < 4096; i += 512) {
        int g = i >> 10, rem = i & 1023;
        int j = rem >> 1, half = rem & 1;
        float4 v = *(const float4*)(w_hh + (((size_t)(d * 4 + g) * H_ + j) * H_ + h0 + half * 4));
        *(float4*)&wS[(g * 512 + j) * 8 + half * 4] = v;
    }

    const int gq  = tid >> 7;
    const int rr  = tid & 127;
    const int hlg = rr >> 4;
    const int bq  = (rr & 15) * 4;

    const int hl = tid >> 6;
    const int b  = tid & 63;

    float bh[4], nz[4];
#pragma unroll
    for (int g = 0; g < 4; g++) {
        bh[g] = b_hh[(size_t)(d * 4 + g) * H_ + h0 + hl];
        nz[g] = noise_hid[((size_t)(d * 4 + g) * B_ + b) * H_ + h0 + hl];
    }
    float hreg = 0.f, creg = 0.f;
    float* outp = layer ? out : g_hs0;

    __syncthreads();

    for (int s = 0; s < T_; s++) {
        const int t = d ? (T_ - 1 - s) : s;
        const float* hn_in  = g_hn[s & 1];
        float*       hn_out = g_hn[(s + 1) & 1];

        float acc0 = 0.f, acc1 = 0.f, acc2 = 0.f, acc3 = 0.f;

#pragma unroll
        for (int k = 0; k < 8; k++) {
            int i = tid + k * 512;
            int g = i >> 10, jj = (i >> 4) & 63, b4 = (i & 15) * 4;
            cp_async16(&hnS[(g * JC + jj) * B_ + b4],
                       hn_in + (((size_t)(d * 4 + g) * H_) + jj) * B_ + b4);
        }
        CP_COMMIT();

        for (int c = 0; c < NCHUNK; c++) {
            if (c + 1 < NCHUNK) {
                float* buf = hnS + ((c + 1) & 1) * HNBUF;
#pragma unroll
                for (int k = 0; k < 8; k++) {
                    int i = tid + k * 512;
                    int g = i >> 10, jj = (i >> 4) & 63, b4 = (i & 15) * 4;
                    cp_async16(&buf[(g * JC + jj) * B_ + b4],
                               hn_in + (((size_t)(d * 4 + g) * H_) + (c + 1) * JC + jj) * B_ + b4);
                }
                CP_COMMIT();
                CP_WAIT1();
            } else {
                CP_WAIT0();
            }
            __syncthreads();

            const float* hb = hnS + (c & 1) * HNBUF + gq * (JC * B_);
            const float* wr = wS + (gq * 512 + c * JC) * 8 + hlg;
#pragma unroll 8
            for (int jj = 0; jj < JC; jj++) {
                float4 a = *(const float4*)(hb + jj * B_ + bq);
                float  w = wr[jj * 8];
                acc0 += a.x * w; acc1 += a.y * w; acc2 += a.z * w; acc3 += a.w * w;
            }
            __syncthreads();
        }

        gBuf[(gq * 8 + hlg) * B_ + bq + 0] = acc0;
        gBuf[(gq * 8 + hlg) * B_ + bq + 1] = acc1;
        gBuf[(gq * 8 + hlg) * B_ + bq + 2] = acc2;
        gBuf[(gq * 8 + hlg) * B_ + bq + 3] = acc3;
        __syncthreads();

        const size_t gxbase = ((size_t)t * 8 + d * 4) * (H_ * B_) + (size_t)(h0 + hl) * B_ + b;
        float x0 = gBuf[(0 * 8 + hl) * B_ + b] + g_gx[gxbase + 0 * (H_ * B_)] + bh[0];
        float x1 = gBuf[(1 * 8 + hl) * B_ + b] + g_gx[gxbase + 1 * (H_ * B_)] + bh[1];
        float x2 = gBuf[(2 * 8 + hl) * B_ + b] + g_gx[gxbase + 2 * (H_ * B_)] + bh[2];
        float x3 = gBuf[(3 * 8 + hl) * B_ + b] + g_gx[gxbase + 3 * (H_ * B_)] + bh[3];

        float ig = 1.f / (1.f + __expf(-x0));
        float fg = 1.f / (1.f + __expf(-x1));
        float gt = tanhf(x2);
        float og = 1.f / (1.f + __expf(-x3));

        float cn = fg * creg + ig * gt;
        float hv = og * tanhf(cn);
        float mt = mask[(size_t)t * B_ + b];
        hreg = hv * mt + hreg * (1.f - mt);
        creg = cn * mt + creg * (1.f - mt);

        const size_t nb = ((size_t)(d * 4) * H_ + h0 + hl) * B_ + b;
        hn_out[nb + 0 * (H_ * B_)] = hreg * nz[0];
        hn_out[nb + 1 * (H_ * B_)] = hreg * nz[1];
        hn_out[nb + 2 * (H_ * B_)] = hreg * nz[2];
        hn_out[nb + 3 * (H_ * B_)] = hreg * nz[3];

        __syncthreads();
        gBuf[b * 8 + hl] = hreg;
        __syncthreads();
        if (tid < 128) {
            int bb = tid >> 1, q = tid & 1;
            float4 v = *(const float4*)&gBuf[bb * 8 + q * 4];
            *(float4*)(outp + ((size_t)t * B_ + bb) * (2 * H_) + (size_t)d * H_ + h0 + q * 4) = v;
        }

        if (s == T_ - 1) {
            g_h[layer][((size_t)d * B_ + b) * H_ + h0 + hl] = hreg;
            g_c[layer][((size_t)d * B_ + b) * H_ + h0 + hl] = creg;
        }

        __threadfence();
        __syncthreads();
        if (tid == 0) {
            unsigned a = atomicAdd(&g_bar_cnt, 1u);
            if (a == (unsigned)(NBLK * (s + 1)) - 1u) {
                g_bar_gen = (unsigned)(s + 1);
            } else {
                while (g_bar_gen < (unsigned)(s + 1)) { }
            }
            __threadfence();
        }
        __syncthreads();
    }
}

// ---------------- finalize ----------------
__global__ void final_kernel(float* __restrict__ out) {
    int i = blockIdx.x * blockDim.x + threadIdx.x;
    if (i >= 4 * B_ * H_) return;
    int l = i >> 16;
    int r = i & 65535;
    size_t O = (size_t)T_ * B_ * 2 * H_;
    out[O + i]          = g_h[l][r];
    out[O + 131072 + i] = g_c[l][r];
}

// ---------------- launch ----------------
extern "C" void kernel_launch(void* const* d_in, const int* in_sizes, int n_in,
                              void* d_out, int out_size) {
    const float* x            = (const float*)d_in[0];
    const float* mask         = (const float*)d_in[1];
    const float* w_ih_l0      = (const float*)d_in[2];
    const float* w_hh_l0      = (const float*)d_in[3];
    const float* b_ih_l0      = (const float*)d_in[4];
    const float* b_hh_l0      = (const float*)d_in[5];
    const float* noise_in_l0  = (const float*)d_in[6];
    const float* noise_hid_l0 = (const float*)d_in[7];
    const float* w_ih_l1      = (const float*)d_in[8];
    const float* w_hh_l1      = (const float*)d_in[9];
    const float* b_ih_l1      = (const float*)d_in[10];
    const float* b_hh_l1      = (const float*)d_in[11];
    const float* noise_in_l1  = (const float*)d_in[12];
    const float* noise_hid_l1 = (const float*)d_in[13];
    float* out = (float*)d_out;

    const int SCAN_SMEM = (16384 + 2 * HNBUF + 2048) * sizeof(float);   // 204800 B
    cudaFuncSetAttribute(scan_kernel, cudaFuncAttributeMaxDynamicSharedMemorySize, SCAN_SMEM);
    const int GX_SMEM = (4 * 16 * AST + 4 * 16 * BST) * sizeof(float);  // 51200 B
    cudaFuncSetAttribute(gx_tf32_kernel, cudaFuncAttributeMaxDynamicSharedMemorySize, GX_SMEM);

    dim3 gxGrid(8, 128, 8);   // (n-tiles, m-tiles over T*B, dg)

    // ----- layer 0 -----
    init_kernel<<<512, 512>>>(0);
    gx_tf32_kernel<<<gxGrid, 256, GX_SMEM>>>(x, noise_in_l0, w_ih_l0, b_ih_l0, IN_, 0);
    scan_kernel<<<NBLK, 512, SCAN_SMEM>>>(w_hh_l0, b_hh_l0, noise_hid_l0, mask, 0, out);

    // ----- layer 1 -----
    init_kernel<<<512, 512>>>(1);
    gx_tf32_kernel<<<gxGrid, 256, GX_SMEM>>>(nullptr, noise_in_l1, w_ih_l1, b_ih_l1, 2 * H_, 1);
    scan_kernel<<<NBLK, 512, SCAN_SMEM>>>(w_hh_l1, b_hh_l1, noise_hid_l1, mask, 1, out);

    final_kernel<<<256, 512>>>(out);
}

// round 11
// speedup vs baseline: 1.2891x; 1.1132x over previous
#include <cuda_runtime.h>
#include <cuda_bf16.h>
#include <math.h>

#define T_  256
#define B_  64
#define IN_ 512
#define H_  512

// ---- scan config ----
#define HT     16                 // h per block
#define NBLK_S 64                 // 2 dirs x 32 h-tiles
#define JCS    32                 // j per chunk
#define JPAD   40                 // padded row length (units of 2B); 80B rows -> 16B aligned
#define NCH    (H_ / JCS)         // 16 chunks

// ---------------- scratch (device globals; no allocation allowed) ----------------
__device__ float  g_gx [(size_t)T_ * 8 * H_ * B_];   // [t][dg][h][b]
__device__ float  g_hs0[(size_t)T_ * B_ * 2 * H_];   // layer-0 output [t][b][d*H+h]
__device__ float  g_h  [2][2 * B_ * H_];
__device__ float  g_c  [2][2 * B_ * H_];
__device__ unsigned short g_hnhi[2][2 * 4 * B_ * H_]; // ping-pong [buf][(d*4+g)*64+b][j] bf16 hi
__device__ unsigned short g_hnlo[2][2 * 4 * B_ * H_]; // bf16 lo
__device__ unsigned g_bar_cnt;
__device__ volatile unsigned g_bar_gen;

// ---------------- helpers ----------------
__device__ __forceinline__ unsigned f2tf32(float x) {
    unsigned r; asm("cvt.rna.tf32.f32 %0, %1;" : "=r"(r) : "f"(x)); return r;
}
__device__ __forceinline__ void cp_async16(void* dst_smem, const void* src) {
    unsigned s = (unsigned)__cvta_generic_to_shared(dst_smem);
    asm volatile("cp.async.cg.shared.global [%0], [%1], 16;\n" :: "r"(s), "l"(src));
}
#define CP_COMMIT()  asm volatile("cp.async.commit_group;\n" ::: "memory")
#define CP_WAIT1()   asm volatile("cp.async.wait_group 1;\n" ::: "memory")
#define CP_WAIT0()   asm volatile("cp.async.wait_group 0;\n" ::: "memory")

#define MMA_TF32(c, a, b) asm volatile( \
    "mma.sync.aligned.m16n8k8.row.col.f32.tf32.tf32.f32 " \
    "{%0,%1,%2,%3}, {%4,%5,%6,%7}, {%8,%9}, {%0,%1,%2,%3};" \
    : "+f"((c)[0]), "+f"((c)[1]), "+f"((c)[2]), "+f"((c)[3]) \
    : "r"((a)[0]), "r"((a)[1]), "r"((a)[2]), "r"((a)[3]), \
      "r"((b)[0]), "r"((b)[1]))

#define MMA_BF16(c, a, b0v, b1v) asm volatile( \
    "mma.sync.aligned.m16n8k16.row.col.f32.bf16.bf16.f32 " \
    "{%0,%1,%2,%3}, {%4,%5,%6,%7}, {%8,%9}, {%0,%1,%2,%3};" \
    : "+f"((c)[0]), "+f"((c)[1]), "+f"((c)[2]), "+f"((c)[3]) \
    : "r"((a).x), "r"((a).y), "r"((a).z), "r"((a).w), \
      "r"(b0v), "r"(b1v))

// ---------------- init ----------------
__global__ void init_kernel(int layer) {
    int i = blockIdx.x * blockDim.x + threadIdx.x;   // 262144 threads
    if (i < 2 * B_ * H_) { g_h[layer][i] = 0.f; g_c[layer][i] = 0.f; }
    if (i < 2 * 4 * B_ * H_) { g_hnhi[0][i] = 0; g_hnlo[0][i] = 0; }
    if (i == 0) { g_bar_cnt = 0; g_bar_gen = 0; }
}

// ---------------- gx GEMM via 3xTF32 tensor cores (unchanged from R6) ----------------
#define AST 132
#define BST 68
__global__ __launch_bounds__(256) void gx_tf32_kernel(
    const float* __restrict__ X,
    const float* __restrict__ noise,
    const float* __restrict__ W,
    const float* __restrict__ bias,
    int K, int layer)
{
    extern __shared__ __align__(16) float sm[];
    float* smA = sm;
    float* smB = sm + 4 * 16 * AST;
    float* Cs  = sm;

    const int dg = blockIdx.z;
    const int n0 = blockIdx.x * 64;
    const int m0 = blockIdx.y * 128;
    const int tid = threadIdx.x;
    const int lane = tid & 31;
    const int warp = tid >> 5;
    const int wm = warp & 3;
    const int wn = warp >> 2;

    const int m_l = tid >> 1;
    const int kq  = (tid & 1) * 8;
    const int k_l = tid >> 4;
    const int n4  = (tid & 15) * 4;

    const float* Xsrc = layer ? g_hs0 : X;
    const float* xrow = Xsrc + (size_t)(m0 + m_l) * K;
    const float* nrow = noise + ((size_t)dg * B_ + ((m0 + m_l) & 63)) * K;
    const float* Wg   = W + (size_t)dg * K * H_;

    unsigned ahi[8], alo[8], bhi[4], blo[4];
    float acc[2][4][4] = {};

    const int nchunks = K >> 4;

    auto loadRegs = [&](int c) {
        int k0 = c * 16;
#pragma unroll
        for (int j = 0; j < 2; j++) {
            float4 xv = *(const float4*)(xrow + k0 + kq + j * 4);
            float4 nv = *(const float4*)(nrow + k0 + kq + j * 4);
            float p[4] = { xv.x * nv.x, xv.y * nv.y, xv.z * nv.z, xv.w * nv.w };
#pragma unroll
            for (int i = 0; i < 4; i++) {
                unsigned h = f2tf32(p[i]);
                ahi[j * 4 + i] = h;
                alo[j * 4 + i] = f2tf32(p[i] - __uint_as_float(h));
            }
        }
        float4 wv = *(const float4*)(Wg + (size_t)(k0 + k_l) * H_ + n0 + n4);
        float q[4] = { wv.x, wv.y, wv.z, wv.w };
#pragma unroll
        for (int i = 0; i < 4; i++) {
            unsigned h = f2tf32(q[i]);
            bhi[i] = h;
            blo[i] = f2tf32(q[i] - __uint_as_float(h));
        }
    };

    auto storeSmem = [&](int buf) {
        float* Ah = smA + buf * 2 * 16 * AST;
        float* Al = Ah + 16 * AST;
#pragma unroll
        for (int j = 0; j < 2; j++)
#pragma unroll
            for (int i = 0; i < 4; i++) {
                Ah[(kq + j * 4 + i) * AST + m_l] = __uint_as_float(ahi[j * 4 + i]);
                Al[(kq + j * 4 + i) * AST + m_l] = __uint_as_float(alo[j * 4 + i]);
            }
        float* Bh = smB + buf * 2 * 16 * BST;
        float* Bl = Bh + 16 * BST;
#pragma unroll
        for (int i = 0; i < 4; i++) {
            Bh[k_l * BST + n4 + i] = __uint_as_float(bhi[i]);
            Bl[k_l * BST + n4 + i] = __uint_as_float(blo[i]);
        }
    };

    auto compute = [&](int buf) {
        const float* Ah = smA + buf * 2 * 16 * AST;
        const float* Al = Ah + 16 * AST;
        const float* Bh = smB + buf * 2 * 16 * BST;
        const float* Bl = Bh + 16 * BST;
#pragma unroll
        for (int ks = 0; ks < 2; ks++) {
            const int kc = ks * 8 + (lane & 3);
            unsigned ah[2][4], al[2][4], bh[4][2], bl[4][2];
#pragma unroll
            for (int im = 0; im < 2; im++) {
                int mr = wm * 32 + im * 16 + (lane >> 2);
                ah[im][0] = __float_as_uint(Ah[kc * AST + mr]);
                ah[im][1] = __float_as_uint(Ah[kc * AST + mr + 8]);
                ah[im][2] = __float_as_uint(Ah[(kc + 4) * AST + mr]);
                ah[im][3] = __float_as_uint(Ah[(kc + 4) * AST + mr + 8]);
                al[im][0] = __float_as_uint(Al[kc * AST + mr]);
                al[im][1] = __float_as_uint(Al[kc * AST + mr + 8]);
                al[im][2] = __float_as_uint(Al[(kc + 4) * AST + mr]);
                al[im][3] = __float_as_uint(Al[(kc + 4) * AST + mr + 8]);
            }
#pragma unroll
            for (int jn = 0; jn < 4; jn++) {
                int nc = wn * 32 + jn * 8 + (lane >> 2);
                bh[jn][0] = __float_as_uint(Bh[kc * BST + nc]);
                bh[jn][1] = __float_as_uint(Bh[(kc + 4) * BST + nc]);
                bl[jn][0] = __float_as_uint(Bl[kc * BST + nc]);
                bl[jn][1] = __float_as_uint(Bl[(kc + 4) * BST + nc]);
            }
#pragma unroll
            for (int im = 0; im < 2; im++)
#pragma unroll
                for (int jn = 0; jn < 4; jn++) {
                    MMA_TF32(acc[im][jn], ah[im], bh[jn]);
                    MMA_TF32(acc[im][jn], ah[im], bl[jn]);
                    MMA_TF32(acc[im][jn], al[im], bh[jn]);
                }
        }
    };

    loadRegs(0);
    storeSmem(0);
    __syncthreads();
    for (int c = 0; c < nchunks; c++) {
        int cur = c & 1;
        bool more = (c + 1 < nchunks);
        if (more) loadRegs(c + 1);
        compute(cur);
        if (more) { __syncthreads(); storeSmem(cur ^ 1); __syncthreads(); }
    }
    __syncthreads();

#pragma unroll
    for (int im = 0; im < 2; im++)
#pragma unroll
        for (int jn = 0; jn < 4; jn++) {
            int r = wm * 32 + im * 16 + (lane >> 2);
            int c2 = wn * 32 + jn * 8 + (lane & 3) * 2;
            Cs[r * 65 + c2]           = acc[im][jn][0];
            Cs[r * 65 + c2 + 1]       = acc[im][jn][1];
            Cs[(r + 8) * 65 + c2]     = acc[im][jn][2];
            Cs[(r + 8) * 65 + c2 + 1] = acc[im][jn][3];
        }
    __syncthreads();

    const int t0 = m0 >> 6;
#pragma unroll
    for (int it = 0; it < 32; it++) {
        int e = tid + it * 256;
        int b  = e & 63;
        int n  = (e >> 6) & 63;
        int tt = e >> 12;
        float v = Cs[(tt * 64 + b) * 65 + n] + __ldg(bias + (size_t)dg * H_ + n0 + n);
        g_gx[(((size_t)(t0 + tt) * 8 + dg) * H_ + n0 + n) * B_ + b] = v;
    }
}

// ---------------- persistent scan with bf16-split tensor-core GEMM ----------------
// 64 blocks = 2 dir x 32 h-tiles (16 h each), 512 threads (16 warps).
// Warp w: gate g = w>>2, b-range q = w&3 -> b in [q*16, q*16+16). Per warp:
// C[16h x 16b] = sum_j W^T[h,j] * hn[j,b], 4 bf16 MMAs per k16 (exact hi/lo split).
__global__ __launch_bounds__(512, 1) void scan_kernel(
    const float* __restrict__ w_hh,       // [2][4][H][H]  ([d][g][j][h])
    const float* __restrict__ b_hh,       // [2][4][H]
    const float* __restrict__ noise_hid,  // [2][4][B][H]
    const float* __restrict__ mask,       // [T][B]
    int layer, float* __restrict__ out)
{
    extern __shared__ __align__(16) char smraw[];
    // Wp:   [2 plane][4 g][32 ks][32 lane][4 u32]  = 131072 B
    // wbuf: 16 warps x [2 buf][2 plane][16 row][JPAD] ushort = 81920 B
    // gBuf: 16384 B (float, gates exchange; reused as output staging)
    unsigned*       Wp    = (unsigned*)smraw;
    unsigned short* wbufs = (unsigned short*)(smraw + 131072);
    float*          gBuf  = (float*)(smraw + 212992);

    const int tid  = threadIdx.x;
    const int d    = blockIdx.x >> 5;
    const int h0   = (blockIdx.x & 31) * HT;
    const int w    = tid >> 5;
    const int lane = tid & 31;
    const int g    = w >> 2;
    const int q    = w & 3;
    const int gid  = lane >> 2;
    const int c2   = lane & 3;
    const int b0w  = q * 16;

    // ---- prepack W fragments (once) ----
    for (int i = tid; i < 4096; i += 512) {
        int gg = i >> 10, ks = (i >> 5) & 31, ln = i & 31;
        int gd = ln >> 2, cc = ln & 3;
        int j0 = ks * 16 + cc * 2;
        const float* Wb = w_hh + ((size_t)(d * 4 + gg) * H_) * H_;
        unsigned rh[4], rl[4];
#pragma unroll
        for (int r = 0; r < 4; r++) {
            int j = j0 + (r >> 1) * 8;
            int h = h0 + gd + (r & 1) * 8;
            float w0 = Wb[(size_t)j * H_ + h];
            float w1 = Wb[(size_t)(j + 1) * H_ + h];
            __nv_bfloat16 h0b = __float2bfloat16(w0);
            __nv_bfloat16 h1b = __float2bfloat16(w1);
            __nv_bfloat16 l0b = __float2bfloat16(w0 - __bfloat162float(h0b));
            __nv_bfloat16 l1b = __float2bfloat16(w1 - __bfloat162float(h1b));
            rh[r] = (unsigned)__bfloat16_as_ushort(h0b) | ((unsigned)__bfloat16_as_ushort(h1b) << 16);
            rl[r] = (unsigned)__bfloat16_as_ushort(l0b) | ((unsigned)__bfloat16_as_ushort(l1b) << 16);
        }
        unsigned* ph = Wp + ((size_t)((0 * 4 + gg) * 32 + ks) * 32 + ln) * 4;
        unsigned* pl = Wp + ((size_t)((1 * 4 + gg) * 32 + ks) * 32 + ln) * 4;
#pragma unroll
        for (int r = 0; r < 4; r++) { ph[r] = rh[r]; pl[r] = rl[r]; }
    }

    // pointwise-side constants: 2 cells per thread: (b, h0+hl), hl = tid>>6 (+8)
    const int b  = tid & 63;
    float bh[2][4], nz[2][4];
#pragma unroll
    for (int k = 0; k < 2; k++) {
        int hl = (tid >> 6) + k * 8;
#pragma unroll
        for (int gg = 0; gg < 4; gg++) {
            bh[k][gg] = b_hh[(size_t)(d * 4 + gg) * H_ + h0 + hl];
            nz[k][gg] = noise_hid[((size_t)(d * 4 + gg) * B_ + b) * H_ + h0 + hl];
        }
    }
    float hreg[2] = {0.f, 0.f}, creg[2] = {0.f, 0.f};
    float* outp = layer ? out : g_hs0;

    unsigned short* wb = wbufs + (size_t)w * 2560;   // per-warp buffer
    const size_t rowbase = (size_t)(d * 4 + g) * B_;

    __syncthreads();

    for (int s = 0; s < T_; s++) {
        const int t = d ? (T_ - 1 - s) : s;
        const unsigned short* hi_in = g_hnhi[s & 1];
        const unsigned short* lo_in = g_hnlo[s & 1];
        unsigned short* hi_out = g_hnhi[(s + 1) & 1];
        unsigned short* lo_out = g_hnlo[(s + 1) & 1];

        float acc[2][4] = {};

        // warp-private cp.async prefetch of chunk c into buf bf
        auto prefetch = [&](int c, int bf) {
#pragma unroll
            for (int it = 0; it < 2; it++) {
                int item = lane + it * 32;
                int r = item >> 2, seg = item & 3;
                size_t gsrc = (rowbase + b0w + r) * H_ + c * JCS + seg * 8;
                cp_async16(wb + ((bf * 2 + 0) * 16 + r) * JPAD + seg * 8, hi_in + gsrc);
                cp_async16(wb + ((bf * 2 + 1) * 16 + r) * JPAD + seg * 8, lo_in + gsrc);
            }
        };

        prefetch(0, 0);
        CP_COMMIT();

        for (int c = 0; c < NCH; c++) {
            if (c + 1 < NCH) {
                prefetch(c + 1, (c + 1) & 1);
                CP_COMMIT();
                CP_WAIT1();
            } else {
                CP_WAIT0();
            }
            __syncwarp();

            const unsigned short* bufh = wb + (((c & 1) * 2 + 0) * 16) * JPAD;
            const unsigned short* bufl = wb + (((c & 1) * 2 + 1) * 16) * JPAD;
#pragma unroll
            for (int ksl = 0; ksl < 2; ksl++) {
                int gk = c * 2 + ksl;
                int j0 = ksl * 16 + c2 * 2;
                uint4 ahi = *(const uint4*)(Wp + ((size_t)((0 * 4 + g) * 32 + gk) * 32 + lane) * 4);
                uint4 alo = *(const uint4*)(Wp + ((size_t)((1 * 4 + g) * 32 + gk) * 32 + lane) * 4);
#pragma unroll
                for (int nt = 0; nt < 2; nt++) {
                    int row = nt * 8 + gid;
                    unsigned bh0 = *(const unsigned*)(bufh + row * JPAD + j0);
                    unsigned bh1 = *(const unsigned*)(bufh + row * JPAD + j0 + 8);
                    unsigned bl0 = *(const unsigned*)(bufl + row * JPAD + j0);
                    unsigned bl1 = *(const unsigned*)(bufl + row * JPAD + j0 + 8);
                    MMA_BF16(acc[nt], ahi, bh0, bh1);
                    MMA_BF16(acc[nt], ahi, bl0, bl1);
                    MMA_BF16(acc[nt], alo, bh0, bh1);
                    MMA_BF16(acc[nt], alo, bl0, bl1);
                }
            }
            __syncwarp();
        }

        // ---- gate exchange: C[m=h(16), n=b(8/tile)] -> gBuf[g][h][b] ----
#pragma unroll
        for (int nt = 0; nt < 2; nt++) {
            int bb = b0w + nt * 8 + c2 * 2;
            gBuf[(g * 16 + gid) * 64 + bb]         = acc[nt][0];
            gBuf[(g * 16 + gid) * 64 + bb + 1]     = acc[nt][1];
            gBuf[(g * 16 + gid + 8) * 64 + bb]     = acc[nt][2];
            gBuf[(g * 16 + gid + 8) * 64 + bb + 1] = acc[nt][3];
        }
        __syncthreads();

        // ---- LSTM pointwise: 2 cells per thread ----
        const float mt = mask[(size_t)t * B_ + b];
        float hloc[2];
#pragma unroll
        for (int k = 0; k < 2; k++) {
            int hl = (tid >> 6) + k * 8;
            size_t gxb = ((size_t)t * 8 + d * 4) * (H_ * B_) + (size_t)(h0 + hl) * B_ + b;
            float x0 = gBuf[(0 * 16 + hl) * 64 + b] + g_gx[gxb + 0 * (size_t)(H_ * B_)] + bh[k][0];
            float x1 = gBuf[(1 * 16 + hl) * 64 + b] + g_gx[gxb + 1 * (size_t)(H_ * B_)] + bh[k][1];
            float x2 = gBuf[(2 * 16 + hl) * 64 + b] + g_gx[gxb + 2 * (size_t)(H_ * B_)] + bh[k][2];
            float x3 = gBuf[(3 * 16 + hl) * 64 + b] + g_gx[gxb + 3 * (size_t)(H_ * B_)] + bh[k][3];

            float ig = 1.f / (1.f + __expf(-x0));
            float fg = 1.f / (1.f + __expf(-x1));
            float gt = tanhf(x2);
            float og = 1.f / (1.f + __expf(-x3));

            float cn = fg * creg[k] + ig * gt;
            float hv = og * tanhf(cn);
            hreg[k] = hv * mt + hreg[k] * (1.f - mt);
            creg[k] = cn * mt + creg[k] * (1.f - mt);
            hloc[k] = hreg[k];

            // next-step hn (bf16 hi/lo planes)
#pragma unroll
            for (int gg = 0; gg < 4; gg++) {
                float v = hreg[k] * nz[k][gg];
                __nv_bfloat16 vh = __float2bfloat16(v);
                __nv_bfloat16 vl = __float2bfloat16(v - __bfloat162float(vh));
                size_t ni = ((size_t)(d * 4 + gg) * B_ + b) * H_ + h0 + (tid >> 6) + k * 8;
                hi_out[ni] = __bfloat16_as_ushort(vh);
                lo_out[ni] = __bfloat16_as_ushort(vl);
            }

            if (s == T_ - 1) {
                size_t si = ((size_t)d * B_ + b) * H_ + h0 + (tid >> 6) + k * 8;
                g_h[layer][si] = hreg[k];
                g_c[layer][si] = creg[k];
            }
        }

        // ---- staged, vectorized output write (reuse gBuf; pad 20) ----
        __syncthreads();
#pragma unroll
        for (int k = 0; k < 2; k++)
            gBuf[b * 20 + (tid >> 6) + k * 8] = hloc[k];
        __syncthreads();
        if (tid < 256) {
            int bb = tid >> 2, qq = tid & 3;
            float4 v = *(const float4*)&gBuf[bb * 20 + qq * 4];
            *(float4*)(outp + ((size_t)t * B_ + bb) * (2 * H_) + (size_t)d * H_ + h0 + qq * 4) = v;
        }

        // ---- grid barrier ----
        __threadfence();
        __syncthreads();
        if (tid == 0) {
            unsigned a = atomicAdd(&g_bar_cnt, 1u);
            if (a == (unsigned)(NBLK_S * (s + 1)) - 1u) {
                g_bar_gen = (unsigned)(s + 1);
            } else {
                while (g_bar_gen < (unsigned)(s + 1)) { }
            }
            __threadfence();
        }
        __syncthreads();
    }
}

// ---------------- finalize ----------------
__global__ void final_kernel(float* __restrict__ out) {
    int i = blockIdx.x * blockDim.x + threadIdx.x;
    if (i >= 4 * B_ * H_) return;
    int l = i >> 16;
    int r = i & 65535;
    size_t O = (size_t)T_ * B_ * 2 * H_;
    out[O + i]          = g_h[l][r];
    out[O + 131072 + i] = g_c[l][r];
}

// ---------------- launch ----------------
extern "C" void kernel_launch(void* const* d_in, const int* in_sizes, int n_in,
                              void* d_out, int out_size) {
    const float* x            = (const float*)d_in[0];
    const float* mask         = (const float*)d_in[1];
    const float* w_ih_l0      = (const float*)d_in[2];
    const float* w_hh_l0      = (const float*)d_in[3];
    const float* b_ih_l0      = (const float*)d_in[4];
    const float* b_hh_l0      = (const float*)d_in[5];
    const float* noise_in_l0  = (const float*)d_in[6];
    const float* noise_hid_l0 = (const float*)d_in[7];
    const float* w_ih_l1      = (const float*)d_in[8];
    const float* w_hh_l1      = (const float*)d_in[9];
    const float* b_ih_l1      = (const float*)d_in[10];
    const float* b_hh_l1      = (const float*)d_in[11];
    const float* noise_in_l1  = (const float*)d_in[12];
    const float* noise_hid_l1 = (const float*)d_in[13];
    float* out = (float*)d_out;

    const int SCAN_SMEM = 131072 + 81920 + 16384;                       // 229376 B
    cudaFuncSetAttribute(scan_kernel, cudaFuncAttributeMaxDynamicSharedMemorySize, SCAN_SMEM);
    const int GX_SMEM = (4 * 16 * AST + 4 * 16 * BST) * sizeof(float);  // 51200 B
    cudaFuncSetAttribute(gx_tf32_kernel, cudaFuncAttributeMaxDynamicSharedMemorySize, GX_SMEM);

    dim3 gxGrid(8, 128, 8);

    // ----- layer 0 -----
    init_kernel<<<512, 512>>>(0);
    gx_tf32_kernel<<<gxGrid, 256, GX_SMEM>>>(x, noise_in_l0, w_ih_l0, b_ih_l0, IN_, 0);
    scan_kernel<<<NBLK_S, 512, SCAN_SMEM>>>(w_hh_l0, b_hh_l0, noise_hid_l0, mask, 0, out);

    // ----- layer 1 -----
    init_kernel<<<512, 512>>>(1);
    gx_tf32_kernel<<<gxGrid, 256, GX_SMEM>>>(nullptr, noise_in_l1, w_ih_l1, b_ih_l1, 2 * H_, 1);
    scan_kernel<<<NBLK_S, 512, SCAN_SMEM>>>(w_hh_l1, b_hh_l1, noise_hid_l1, mask, 1, out);

    final_kernel<<<256, 512>>>(out);
}

// round 12
// speedup vs baseline: 1.6100x; 1.2489x over previous
#include <cuda_runtime.h>
#include <cuda_bf16.h>
#include <math.h>

#define T_  256
#define B_  64
#define IN_ 512
#define H_  512

// ---- scan config ----
#define HT     16                 // h per block
#define NBLK_S 64                 // 2 dirs x 32 h-tiles
#define JCS    32                 // j per chunk
#define JPAD   32                 // row length in ushorts (64 B rows, 16B aligned)
#define NCH    (H_ / JCS)         // 16 chunks

// ---------------- scratch (device globals; no allocation allowed) ----------------
__device__ float  g_gx [(size_t)T_ * 8 * H_ * B_];   // [t][dg][h][b]
__device__ float  g_hs0[(size_t)T_ * B_ * 2 * H_];   // layer-0 output [t][b][d*H+h]
__device__ float  g_h  [2][2 * B_ * H_];
__device__ float  g_c  [2][2 * B_ * H_];
__device__ unsigned short g_hnhi[2][2 * 4 * B_ * H_]; // [buf][(d*4+g)*64+b][j] bf16 hi
__device__ unsigned short g_hnlo[2][2 * 4 * B_ * H_]; // bf16 lo
__device__ unsigned g_bar_cnt;
__device__ unsigned g_bar_gen;

// ---------------- helpers ----------------
__device__ __forceinline__ unsigned f2tf32(float x) {
    unsigned r; asm("cvt.rna.tf32.f32 %0, %1;" : "=r"(r) : "f"(x)); return r;
}
__device__ __forceinline__ void cp_async16(void* dst_smem, const void* src) {
    unsigned s = (unsigned)__cvta_generic_to_shared(dst_smem);
    asm volatile("cp.async.cg.shared.global [%0], [%1], 16;\n" :: "r"(s), "l"(src));
}
#define CP_COMMIT()  asm volatile("cp.async.commit_group;\n" ::: "memory")
#define CP_WAIT1()   asm volatile("cp.async.wait_group 1;\n" ::: "memory")
#define CP_WAIT0()   asm volatile("cp.async.wait_group 0;\n" ::: "memory")

#define MMA_TF32(c, a, b) asm volatile( \
    "mma.sync.aligned.m16n8k8.row.col.f32.tf32.tf32.f32 " \
    "{%0,%1,%2,%3}, {%4,%5,%6,%7}, {%8,%9}, {%0,%1,%2,%3};" \
    : "+f"((c)[0]), "+f"((c)[1]), "+f"((c)[2]), "+f"((c)[3]) \
    : "r"((a)[0]), "r"((a)[1]), "r"((a)[2]), "r"((a)[3]), \
      "r"((b)[0]), "r"((b)[1]))

#define MMA_BF16(c, a, b0v, b1v) asm volatile( \
    "mma.sync.aligned.m16n8k16.row.col.f32.bf16.bf16.f32 " \
    "{%0,%1,%2,%3}, {%4,%5,%6,%7}, {%8,%9}, {%0,%1,%2,%3};" \
    : "+f"((c)[0]), "+f"((c)[1]), "+f"((c)[2]), "+f"((c)[3]) \
    : "r"((a).x), "r"((a).y), "r"((a).z), "r"((a).w), \
      "r"(b0v), "r"(b1v))

// ---------------- init ----------------
__global__ void init_kernel(int layer) {
    int i = blockIdx.x * blockDim.x + threadIdx.x;   // 262144 threads
    if (i < 2 * B_ * H_) { g_h[layer][i] = 0.f; g_c[layer][i] = 0.f; }
    if (i < 2 * 4 * B_ * H_) { g_hnhi[0][i] = 0; g_hnlo[0][i] = 0; }
    if (i == 0) { g_bar_cnt = 0; g_bar_gen = 0; }
}

// ---------------- gx GEMM via 3xTF32 tensor cores (unchanged) ----------------
#define AST 132
#define BST 68
__global__ __launch_bounds__(256) void gx_tf32_kernel(
    const float* __restrict__ X,
    const float* __restrict__ noise,
    const float* __restrict__ W,
    const float* __restrict__ bias,
    int K, int layer)
{
    extern __shared__ __align__(16) float sm[];
    float* smA = sm;
    float* smB = sm + 4 * 16 * AST;
    float* Cs  = sm;

    const int dg = blockIdx.z;
    const int n0 = blockIdx.x * 64;
    const int m0 = blockIdx.y * 128;
    const int tid = threadIdx.x;
    const int lane = tid & 31;
    const int warp = tid >> 5;
    const int wm = warp & 3;
    const int wn = warp >> 2;

    const int m_l = tid >> 1;
    const int kq  = (tid & 1) * 8;
    const int k_l = tid >> 4;
    const int n4  = (tid & 15) * 4;

    const float* Xsrc = layer ? g_hs0 : X;
    const float* xrow = Xsrc + (size_t)(m0 + m_l) * K;
    const float* nrow = noise + ((size_t)dg * B_ + ((m0 + m_l) & 63)) * K;
    const float* Wg   = W + (size_t)dg * K * H_;

    unsigned ahi[8], alo[8], bhi[4], blo[4];
    float acc[2][4][4] = {};

    const int nchunks = K >> 4;

    auto loadRegs = [&](int c) {
        int k0 = c * 16;
#pragma unroll
        for (int j = 0; j < 2; j++) {
            float4 xv = *(const float4*)(xrow + k0 + kq + j * 4);
            float4 nv = *(const float4*)(nrow + k0 + kq + j * 4);
            float p[4] = { xv.x * nv.x, xv.y * nv.y, xv.z * nv.z, xv.w * nv.w };
#pragma unroll
            for (int i = 0; i < 4; i++) {
                unsigned h = f2tf32(p[i]);
                ahi[j * 4 + i] = h;
                alo[j * 4 + i] = f2tf32(p[i] - __uint_as_float(h));
            }
        }
        float4 wv = *(const float4*)(Wg + (size_t)(k0 + k_l) * H_ + n0 + n4);
        float q[4] = { wv.x, wv.y, wv.z, wv.w };
#pragma unroll
        for (int i = 0; i < 4; i++) {
            unsigned h = f2tf32(q[i]);
            bhi[i] = h;
            blo[i] = f2tf32(q[i] - __uint_as_float(h));
        }
    };

    auto storeSmem = [&](int buf) {
        float* Ah = smA + buf * 2 * 16 * AST;
        float* Al = Ah + 16 * AST;
#pragma unroll
        for (int j = 0; j < 2; j++)
#pragma unroll
            for (int i = 0; i < 4; i++) {
                Ah[(kq + j * 4 + i) * AST + m_l] = __uint_as_float(ahi[j * 4 + i]);
                Al[(kq + j * 4 + i) * AST + m_l] = __uint_as_float(alo[j * 4 + i]);
            }
        float* Bh = smB + buf * 2 * 16 * BST;
        float* Bl = Bh + 16 * BST;
#pragma unroll
        for (int i = 0; i < 4; i++) {
            Bh[k_l * BST + n4 + i] = __uint_as_float(bhi[i]);
            Bl[k_l * BST + n4 + i] = __uint_as_float(blo[i]);
        }
    };

    auto compute = [&](int buf) {
        const float* Ah = smA + buf * 2 * 16 * AST;
        const float* Al = Ah + 16 * AST;
        const float* Bh = smB + buf * 2 * 16 * BST;
        const float* Bl = Bh + 16 * BST;
#pragma unroll
        for (int ks = 0; ks < 2; ks++) {
            const int kc = ks * 8 + (lane & 3);
            unsigned ah[2][4], al[2][4], bh[4][2], bl[4][2];
#pragma unroll
            for (int im = 0; im < 2; im++) {
                int mr = wm * 32 + im * 16 + (lane >> 2);
                ah[im][0] = __float_as_uint(Ah[kc * AST + mr]);
                ah[im][1] = __float_as_uint(Ah[kc * AST + mr + 8]);
                ah[im][2] = __float_as_uint(Ah[(kc + 4) * AST + mr]);
                ah[im][3] = __float_as_uint(Ah[(kc + 4) * AST + mr + 8]);
                al[im][0] = __float_as_uint(Al[kc * AST + mr]);
                al[im][1] = __float_as_uint(Al[kc * AST + mr + 8]);
                al[im][2] = __float_as_uint(Al[(kc + 4) * AST + mr]);
                al[im][3] = __float_as_uint(Al[(kc + 4) * AST + mr + 8]);
            }
#pragma unroll
            for (int jn = 0; jn < 4; jn++) {
                int nc = wn * 32 + jn * 8 + (lane >> 2);
                bh[jn][0] = __float_as_uint(Bh[kc * BST + nc]);
                bh[jn][1] = __float_as_uint(Bh[(kc + 4) * BST + nc]);
                bl[jn][0] = __float_as_uint(Bl[kc * BST + nc]);
                bl[jn][1] = __float_as_uint(Bl[(kc + 4) * BST + nc]);
            }
#pragma unroll
            for (int im = 0; im < 2; im++)
#pragma unroll
                for (int jn = 0; jn < 4; jn++) {
                    MMA_TF32(acc[im][jn], ah[im], bh[jn]);
                    MMA_TF32(acc[im][jn], ah[im], bl[jn]);
                    MMA_TF32(acc[im][jn], al[im], bh[jn]);
                }
        }
    };

    loadRegs(0);
    storeSmem(0);
    __syncthreads();
    for (int c = 0; c < nchunks; c++) {
        int cur = c & 1;
        bool more = (c + 1 < nchunks);
        if (more) loadRegs(c + 1);
        compute(cur);
        if (more) { __syncthreads(); storeSmem(cur ^ 1); __syncthreads(); }
    }
    __syncthreads();

#pragma unroll
    for (int im = 0; im < 2; im++)
#pragma unroll
        for (int jn = 0; jn < 4; jn++) {
            int r = wm * 32 + im * 16 + (lane >> 2);
            int c2 = wn * 32 + jn * 8 + (lane & 3) * 2;
            Cs[r * 65 + c2]           = acc[im][jn][0];
            Cs[r * 65 + c2 + 1]       = acc[im][jn][1];
            Cs[(r + 8) * 65 + c2]     = acc[im][jn][2];
            Cs[(r + 8) * 65 + c2 + 1] = acc[im][jn][3];
        }
    __syncthreads();

    const int t0 = m0 >> 6;
#pragma unroll
    for (int it = 0; it < 32; it++) {
        int e = tid + it * 256;
        int b  = e & 63;
        int n  = (e >> 6) & 63;
        int tt = e >> 12;
        float v = Cs[(tt * 64 + b) * 65 + n] + __ldg(bias + (size_t)dg * H_ + n0 + n);
        g_gx[(((size_t)(t0 + tt) * 8 + dg) * H_ + n0 + n) * B_ + b] = v;
    }
}

// ---------------- persistent scan: bf16-split MMA + coalesced hn + gx prefetch ----------------
// 64 blocks = 2 dir x 32 h-tiles (16 h each), 512 threads (16 warps).
// smem: Wp 131072 | wbufs 65536 (reused post-GEMM as sHi/sLo/sOut) | gBuf 16384 | gxBuf 16384
__global__ __launch_bounds__(512, 1) void scan_kernel(
    const float* __restrict__ w_hh,       // [2][4][H][H]  ([d][g][j][h])
    const float* __restrict__ b_hh,       // [2][4][H]
    const float* __restrict__ noise_hid,  // [2][4][B][H]
    const float* __restrict__ mask,       // [T][B]
    int layer, float* __restrict__ out)
{
    extern __shared__ __align__(16) char smraw[];
    unsigned*       Wp    = (unsigned*)smraw;                       // 131072 B
    unsigned short* wbufs = (unsigned short*)(smraw + 131072);      // 65536 B
    float*          gBuf  = (float*)(smraw + 196608);               // 16384 B
    float*          gxBuf = (float*)(smraw + 212992);               // 16384 B
    unsigned*       sHi32 = (unsigned*)(smraw + 131072);            // 8192 B (reuse wbufs)
    unsigned*       sLo32 = (unsigned*)(smraw + 131072 + 8192);     // 8192 B
    float*          sOut  = (float*)(smraw + 131072 + 16384);       // 5120 B

    const int tid  = threadIdx.x;
    const int d    = blockIdx.x >> 5;
    const int h0   = (blockIdx.x & 31) * HT;
    const int w    = tid >> 5;
    const int lane = tid & 31;
    const int g    = w >> 2;
    const int q    = w & 3;
    const int gid  = lane >> 2;
    const int c2   = lane & 3;
    const int b0w  = q * 16;

    // ---- prepack W fragments (once) ----
    for (int i = tid; i < 4096; i += 512) {
        int gg = i >> 10, ks = (i >> 5) & 31, ln = i & 31;
        int gd = ln >> 2, cc = ln & 3;
        int j0 = ks * 16 + cc * 2;
        const float* Wb = w_hh + ((size_t)(d * 4 + gg) * H_) * H_;
        unsigned rh[4], rl[4];
#pragma unroll
        for (int r = 0; r < 4; r++) {
            int j = j0 + (r >> 1) * 8;
            int h = h0 + gd + (r & 1) * 8;
            float w0 = Wb[(size_t)j * H_ + h];
            float w1 = Wb[(size_t)(j + 1) * H_ + h];
            __nv_bfloat16 h0b = __float2bfloat16(w0);
            __nv_bfloat16 h1b = __float2bfloat16(w1);
            __nv_bfloat16 l0b = __float2bfloat16(w0 - __bfloat162float(h0b));
            __nv_bfloat16 l1b = __float2bfloat16(w1 - __bfloat162float(h1b));
            rh[r] = (unsigned)__bfloat16_as_ushort(h0b) | ((unsigned)__bfloat16_as_ushort(h1b) << 16);
            rl[r] = (unsigned)__bfloat16_as_ushort(l0b) | ((unsigned)__bfloat16_as_ushort(l1b) << 16);
        }
        unsigned* ph = Wp + ((size_t)((0 * 4 + gg) * 32 + ks) * 32 + ln) * 4;
        unsigned* pl = Wp + ((size_t)((1 * 4 + gg) * 32 + ks) * 32 + ln) * 4;
#pragma unroll
        for (int r = 0; r < 4; r++) { ph[r] = rh[r]; pl[r] = rl[r]; }
    }

    // pointwise side: 2 adjacent cells per thread: (b, h0 + hp*2 + k)
    const int b  = tid & 63;
    const int hp = tid >> 6;            // 0..7
    float bh[2][4], nz[2][4];
#pragma unroll
    for (int k = 0; k < 2; k++) {
        int hl = hp * 2 + k;
#pragma unroll
        for (int gg = 0; gg < 4; gg++) {
            bh[k][gg] = b_hh[(size_t)(d * 4 + gg) * H_ + h0 + hl];
            nz[k][gg] = noise_hid[((size_t)(d * 4 + gg) * B_ + b) * H_ + h0 + hl];
        }
    }
    float hreg[2] = {0.f, 0.f}, creg[2] = {0.f, 0.f};
    float* outp = layer ? out : g_hs0;

    unsigned short* wb = wbufs + (size_t)w * 2048;   // per-warp buffer (4096 B)
    const size_t rowbase = (size_t)(d * 4 + g) * B_;

    __syncthreads();

    for (int s = 0; s < T_; s++) {
        const int t = d ? (T_ - 1 - s) : s;
        const unsigned short* hi_in = g_hnhi[s & 1];
        const unsigned short* lo_in = g_hnlo[s & 1];
        unsigned short* hi_out = g_hnhi[(s + 1) & 1];
        unsigned short* lo_out = g_hnlo[(s + 1) & 1];

        // ---- gx prefetch (16 KB) -> gxBuf, overlapped with GEMM ----
        {
            const float* gsrc = g_gx + ((size_t)t * 8 + d * 4) * (size_t)(H_ * B_) + (size_t)h0 * B_;
#pragma unroll
            for (int i = 0; i < 2; i++) {
                int e = tid + i * 512;           // 0..1023
                int gg = e >> 8, hh = (e >> 4) & 15, sg = e & 15;
                cp_async16(gxBuf + (gg * 16 + hh) * 64 + sg * 4,
                           gsrc + (size_t)gg * (H_ * B_) + (size_t)hh * B_ + sg * 4);
            }
            CP_COMMIT();
        }

        float acc[2][4] = {};

        auto prefetch = [&](int c, int bf) {
#pragma unroll
            for (int it = 0; it < 2; it++) {
                int item = lane + it * 32;
                int r = item >> 2, seg = item & 3;
                size_t gsrc = (rowbase + b0w + r) * H_ + c * JCS + seg * 8;
                cp_async16(wb + ((bf * 2 + 0) * 16 + r) * JPAD + seg * 8, hi_in + gsrc);
                cp_async16(wb + ((bf * 2 + 1) * 16 + r) * JPAD + seg * 8, lo_in + gsrc);
            }
        };

        prefetch(0, 0);
        CP_COMMIT();

        for (int c = 0; c < NCH; c++) {
            if (c + 1 < NCH) {
                prefetch(c + 1, (c + 1) & 1);
                CP_COMMIT();
                CP_WAIT1();
            } else {
                CP_WAIT0();
            }
            __syncwarp();

            const unsigned short* bufh = wb + (((c & 1) * 2 + 0) * 16) * JPAD;
            const unsigned short* bufl = wb + (((c & 1) * 2 + 1) * 16) * JPAD;
#pragma unroll
            for (int ksl = 0; ksl < 2; ksl++) {
                int gk = c * 2 + ksl;
                int j0 = ksl * 16 + c2 * 2;
                uint4 ahi = *(const uint4*)(Wp + ((size_t)((0 * 4 + g) * 32 + gk) * 32 + lane) * 4);
                uint4 alo = *(const uint4*)(Wp + ((size_t)((1 * 4 + g) * 32 + gk) * 32 + lane) * 4);
#pragma unroll
                for (int nt = 0; nt < 2; nt++) {
                    int row = nt * 8 + gid;
                    unsigned bh0 = *(const unsigned*)(bufh + row * JPAD + j0);
                    unsigned bh1 = *(const unsigned*)(bufh + row * JPAD + j0 + 8);
                    unsigned bl0 = *(const unsigned*)(bufl + row * JPAD + j0);
                    unsigned bl1 = *(const unsigned*)(bufl + row * JPAD + j0 + 8);
                    MMA_BF16(acc[nt], ahi, bh0, bh1);
                    MMA_BF16(acc[nt], ahi, bl0, bl1);
                    MMA_BF16(acc[nt], alo, bh0, bh1);
                }
            }
            __syncwarp();
        }

        // ---- gate exchange ----
#pragma unroll
        for (int nt = 0; nt < 2; nt++) {
            int bb = b0w + nt * 8 + c2 * 2;
            gBuf[(g * 16 + gid) * 64 + bb]         = acc[nt][0];
            gBuf[(g * 16 + gid) * 64 + bb + 1]     = acc[nt][1];
            gBuf[(g * 16 + gid + 8) * 64 + bb]     = acc[nt][2];
            gBuf[(g * 16 + gid + 8) * 64 + bb + 1] = acc[nt][3];
        }
        __syncthreads();   // S1: GEMM + exchange complete; wbufs free; gxBuf ready

        // ---- LSTM pointwise: 2 adjacent cells per thread ----
        const float mt = mask[(size_t)t * B_ + b];
#pragma unroll
        for (int k = 0; k < 2; k++) {
            int hl = hp * 2 + k;
            float x0 = gBuf[(0 * 16 + hl) * 64 + b] + gxBuf[(0 * 16 + hl) * 64 + b] + bh[k][0];
            float x1 = gBuf[(1 * 16 + hl) * 64 + b] + gxBuf[(1 * 16 + hl) * 64 + b] + bh[k][1];
            float x2 = gBuf[(2 * 16 + hl) * 64 + b] + gxBuf[(2 * 16 + hl) * 64 + b] + bh[k][2];
            float x3 = gBuf[(3 * 16 + hl) * 64 + b] + gxBuf[(3 * 16 + hl) * 64 + b] + bh[k][3];

            float ig = 1.f / (1.f + __expf(-x0));
            float fg = 1.f / (1.f + __expf(-x1));
            float gt = tanhf(x2);
            float og = 1.f / (1.f + __expf(-x3));

            float cn = fg * creg[k] + ig * gt;
            float hv = og * tanhf(cn);
            hreg[k] = hv * mt + hreg[k] * (1.f - mt);
            creg[k] = cn * mt + creg[k] * (1.f - mt);

            if (s == T_ - 1) {
                size_t si = ((size_t)d * B_ + b) * H_ + h0 + hl;
                g_h[layer][si] = hreg[k];
                g_c[layer][si] = creg[k];
            }
        }

        // stage hn (packed u32 per j-pair) + output h into smem
#pragma unroll
        for (int gg = 0; gg < 4; gg++) {
            float v0 = hreg[0] * nz[0][gg];
            float v1 = hreg[1] * nz[1][gg];
            __nv_bfloat16 h0b = __float2bfloat16(v0);
            __nv_bfloat16 h1b = __float2bfloat16(v1);
            __nv_bfloat16 l0b = __float2bfloat16(v0 - __bfloat162float(h0b));
            __nv_bfloat16 l1b = __float2bfloat16(v1 - __bfloat162float(h1b));
            sHi32[(gg * 64 + b) * 8 + hp] =
                (unsigned)__bfloat16_as_ushort(h0b) | ((unsigned)__bfloat16_as_ushort(h1b) << 16);
            sLo32[(gg * 64 + b) * 8 + hp] =
                (unsigned)__bfloat16_as_ushort(l0b) | ((unsigned)__bfloat16_as_ushort(l1b) << 16);
        }
        sOut[b * 20 + hp * 2 + 0] = hreg[0];
        sOut[b * 20 + hp * 2 + 1] = hreg[1];
        __syncthreads();   // S2: stages complete

        // ---- cooperative coalesced hn stores ----
        {
            unsigned* ghi = (unsigned*)hi_out;
            unsigned* glo = (unsigned*)lo_out;
#pragma unroll
            for (int i = 0; i < 4; i++) {
                int e = tid + i * 512;           // 0..2047
                int gg = e >> 9, bb = (e >> 3) & 63, p = e & 7;
                size_t gi = ((size_t)(d * 4 + gg) * B_ + bb) * (H_ / 2) + (h0 >> 1) + p;
                ghi[gi] = sHi32[e];
                glo[gi] = sLo32[e];
            }
        }
        __syncthreads();   // S3: hn stores issued block-wide

        if (tid == 0) {
            __threadfence();
            unsigned a = atomicAdd(&g_bar_cnt, 1u);
            if (a == (unsigned)(NBLK_S * (s + 1)) - 1u) {
                asm volatile("st.release.gpu.u32 [%0], %1;" :: "l"(&g_bar_gen), "r"((unsigned)(s + 1)) : "memory");
            } else {
                unsigned v;
                do {
                    asm volatile("ld.acquire.gpu.u32 %0, [%1];" : "=r"(v) : "l"(&g_bar_gen) : "memory");
                } while (v < (unsigned)(s + 1));
            }
        } else if (tid >= 256) {
            // output stores overlapped with tid0's barrier spin (no cross-block consumer)
            int e = tid - 256;
            int bb = e >> 2, qq = e & 3;
            float4 v = *(const float4*)&sOut[bb * 20 + qq * 4];
            *(float4*)(outp + ((size_t)t * B_ + bb) * (2 * H_) + (size_t)d * H_ + h0 + qq * 4) = v;
        }
        __syncthreads();   // S4: barrier released; safe to touch wbufs/gxBuf next step
    }
}

// ---------------- finalize ----------------
__global__ void final_kernel(float* __restrict__ out) {
    int i = blockIdx.x * blockDim.x + threadIdx.x;
    if (i >= 4 * B_ * H_) return;
    int l = i >> 16;
    int r = i & 65535;
    size_t O = (size_t)T_ * B_ * 2 * H_;
    out[O + i]          = g_h[l][r];
    out[O + 131072 + i] = g_c[l][r];
}

// ---------------- launch ----------------
extern "C" void kernel_launch(void* const* d_in, const int* in_sizes, int n_in,
                              void* d_out, int out_size) {
    const float* x            = (const float*)d_in[0];
    const float* mask         = (const float*)d_in[1];
    const float* w_ih_l0      = (const float*)d_in[2];
    const float* w_hh_l0      = (const float*)d_in[3];
    const float* b_ih_l0      = (const float*)d_in[4];
    const float* b_hh_l0      = (const float*)d_in[5];
    const float* noise_in_l0  = (const float*)d_in[6];
    const float* noise_hid_l0 = (const float*)d_in[7];
    const float* w_ih_l1      = (const float*)d_in[8];
    const float* w_hh_l1      = (const float*)d_in[9];
    const float* b_ih_l1      = (const float*)d_in[10];
    const float* b_hh_l1      = (const float*)d_in[11];
    const float* noise_in_l1  = (const float*)d_in[12];
    const float* noise_hid_l1 = (const float*)d_in[13];
    float* out = (float*)d_out;

    const int SCAN_SMEM = 131072 + 65536 + 16384 + 16384;               // 229376 B
    cudaFuncSetAttribute(scan_kernel, cudaFuncAttributeMaxDynamicSharedMemorySize, SCAN_SMEM);
    const int GX_SMEM = (4 * 16 * AST + 4 * 16 * BST) * sizeof(float);  // 51200 B
    cudaFuncSetAttribute(gx_tf32_kernel, cudaFuncAttributeMaxDynamicSharedMemorySize, GX_SMEM);

    dim3 gxGrid(8, 128, 8);

    // ----- layer 0 -----
    init_kernel<<<512, 512>>>(0);
    gx_tf32_kernel<<<gxGrid, 256, GX_SMEM>>>(x, noise_in_l0, w_ih_l0, b_ih_l0, IN_, 0);
    scan_kernel<<<NBLK_S, 512, SCAN_SMEM>>>(w_hh_l0, b_hh_l0, noise_hid_l0, mask, 0, out);

    // ----- layer 1 -----
    init_kernel<<<512, 512>>>(1);
    gx_tf32_kernel<<<gxGrid, 256, GX_SMEM>>>(nullptr, noise_in_l1, w_ih_l1, b_ih_l1, 2 * H_, 1);
    scan_kernel<<<NBLK_S, 512, SCAN_SMEM>>>(w_hh_l1, b_hh_l1, noise_hid_l1, mask, 1, out);

    final_kernel<<<256, 512>>>(out);
}

// round 14
// speedup vs baseline: 1.6111x; 1.0007x over previous
#include <cuda_runtime.h>
#include <cuda_bf16.h>
#include <math.h>

#define T_  256
#define B_  64
#define IN_ 512
#define H_  512

// ---- scan config ----
#define HT     16                 // h per block
#define NBLK_S 64                 // 2 dirs x 32 h-tiles
#define JCS    32                 // j per chunk
#define JPAD   32                 // row length in ushorts (64 B rows, 16B aligned)
#define NCH    (H_ / JCS)         // 16 chunks

// ---------------- scratch (device globals; no allocation allowed) ----------------
__device__ float  g_gx [(size_t)T_ * 8 * H_ * B_];   // [t][dg][h][b]
__device__ float  g_hs0[(size_t)T_ * B_ * 2 * H_];   // layer-0 output [t][b][d*H+h]
__device__ float  g_h  [2][2 * B_ * H_];
__device__ float  g_c  [2][2 * B_ * H_];
__device__ unsigned short g_hnhi[2][2 * 4 * B_ * H_]; // [buf][(d*4+g)*64+b][j] bf16 hi
__device__ unsigned short g_hnlo[2][2 * 4 * B_ * H_]; // bf16 lo
__device__ unsigned g_bar_cnt;
__device__ unsigned g_bar_gen;
__device__ unsigned g_gx_ready[T_ / 2];              // per t-pair completion count (64 = ready)

// ---------------- helpers ----------------
__device__ __forceinline__ unsigned f2tf32(float x) {
    unsigned r; asm("cvt.rna.tf32.f32 %0, %1;" : "=r"(r) : "f"(x)); return r;
}
__device__ __forceinline__ void cp_async16(void* dst_smem, const void* src) {
    unsigned s = (unsigned)__cvta_generic_to_shared(dst_smem);
    asm volatile("cp.async.cg.shared.global [%0], [%1], 16;\n" :: "r"(s), "l"(src));
}
#define CP_COMMIT()  asm volatile("cp.async.commit_group;\n" ::: "memory")
#define CP_WAIT1()   asm volatile("cp.async.wait_group 1;\n" ::: "memory")
#define CP_WAIT0()   asm volatile("cp.async.wait_group 0;\n" ::: "memory")

#define MMA_TF32(c, a, b) asm volatile( \
    "mma.sync.aligned.m16n8k8.row.col.f32.tf32.tf32.f32 " \
    "{%0,%1,%2,%3}, {%4,%5,%6,%7}, {%8,%9}, {%0,%1,%2,%3};" \
    : "+f"((c)[0]), "+f"((c)[1]), "+f"((c)[2]), "+f"((c)[3]) \
    : "r"((a)[0]), "r"((a)[1]), "r"((a)[2]), "r"((a)[3]), \
      "r"((b)[0]), "r"((b)[1]))

#define MMA_BF16(c, a, b0v, b1v) asm volatile( \
    "mma.sync.aligned.m16n8k16.row.col.f32.bf16.bf16.f32 " \
    "{%0,%1,%2,%3}, {%4,%5,%6,%7}, {%8,%9}, {%0,%1,%2,%3};" \
    : "+f"((c)[0]), "+f"((c)[1]), "+f"((c)[2]), "+f"((c)[3]) \
    : "r"((a).x), "r"((a).y), "r"((a).z), "r"((a).w), \
      "r"(b0v), "r"(b1v))

// ---------------- init ----------------
__global__ void init_kernel(int layer) {
    int i = blockIdx.x * blockDim.x + threadIdx.x;   // 262144 threads
    if (i < 2 * B_ * H_) { g_h[layer][i] = 0.f; g_c[layer][i] = 0.f; }
    if (i < 2 * 4 * B_ * H_) { g_hnhi[0][i] = 0; g_hnlo[0][i] = 0; }
    if (i < T_ / 2) g_gx_ready[i] = 0;
    if (i == 0) { g_bar_cnt = 0; g_bar_gen = 0; }
}

// ---------------- gx GEMM via 3xTF32 tensor cores ----------------
// grid (64, 128, 1): x = nt(8) | dg(8) (dg/nt innermost for in-order pair completion),
// y = z-order both-ends-inward over 128 t-pairs. Publishes g_gx_ready[pair] on finish.
#define AST 132
#define BST 68
__global__ __launch_bounds__(256, 2) void gx_tf32_kernel(
    const float* __restrict__ X,
    const float* __restrict__ noise,
    const float* __restrict__ W,
    const float* __restrict__ bias,
    int K, int layer)
{
    extern __shared__ __align__(16) float sm[];
    float* smA = sm;
    float* smB = sm + 4 * 16 * AST;
    float* Cs  = sm;

    const int nt = blockIdx.x & 7;
    const int dg = blockIdx.x >> 3;
    const int n0 = nt * 64;
    const int z  = blockIdx.y;
    const int zi = z >> 1;
    const int t0 = (z & 1) ? (T_ - 2 - 2 * zi) : (2 * zi);
    const int m0 = t0 * 64;

    const int tid = threadIdx.x;
    const int lane = tid & 31;
    const int warp = tid >> 5;
    const int wm = warp & 3;
    const int wn = warp >> 2;

    const int m_l = tid >> 1;
    const int kq  = (tid & 1) * 8;
    const int k_l = tid >> 4;
    const int n4  = (tid & 15) * 4;

    const float* Xsrc = layer ? g_hs0 : X;
    const float* xrow = Xsrc + (size_t)(m0 + m_l) * K;
    const float* nrow = noise + ((size_t)dg * B_ + ((m0 + m_l) & 63)) * K;
    const float* Wg   = W + (size_t)dg * K * H_;

    unsigned ahi[8], alo[8], bhi[4], blo[4];
    float acc[2][4][4] = {};

    const int nchunks = K >> 4;

    auto loadRegs = [&](int c) {
        int k0 = c * 16;
#pragma unroll
        for (int j = 0; j < 2; j++) {
            float4 xv = *(const float4*)(xrow + k0 + kq + j * 4);
            float4 nv = *(const float4*)(nrow + k0 + kq + j * 4);
            float p[4] = { xv.x * nv.x, xv.y * nv.y, xv.z * nv.z, xv.w * nv.w };
#pragma unroll
            for (int i = 0; i < 4; i++) {
                unsigned h = f2tf32(p[i]);
                ahi[j * 4 + i] = h;
                alo[j * 4 + i] = f2tf32(p[i] - __uint_as_float(h));
            }
        }
        float4 wv = *(const float4*)(Wg + (size_t)(k0 + k_l) * H_ + n0 + n4);
        float q[4] = { wv.x, wv.y, wv.z, wv.w };
#pragma unroll
        for (int i = 0; i < 4; i++) {
            unsigned h = f2tf32(q[i]);
            bhi[i] = h;
            blo[i] = f2tf32(q[i] - __uint_as_float(h));
        }
    };

    auto storeSmem = [&](int buf) {
        float* Ah = smA + buf * 2 * 16 * AST;
        float* Al = Ah + 16 * AST;
#pragma unroll
        for (int j = 0; j < 2; j++)
#pragma unroll
            for (int i = 0; i < 4; i++) {
                Ah[(kq + j * 4 + i) * AST + m_l] = __uint_as_float(ahi[j * 4 + i]);
                Al[(kq + j * 4 + i) * AST + m_l] = __uint_as_float(alo[j * 4 + i]);
            }
        float* Bh = smB + buf * 2 * 16 * BST;
        float* Bl = Bh + 16 * BST;
#pragma unroll
        for (int i = 0; i < 4; i++) {
            Bh[k_l * BST + n4 + i] = __uint_as_float(bhi[i]);
            Bl[k_l * BST + n4 + i] = __uint_as_float(blo[i]);
        }
    };

    auto compute = [&](int buf) {
        const float* Ah = smA + buf * 2 * 16 * AST;
        const float* Al = Ah + 16 * AST;
        const float* Bh = smB + buf * 2 * 16 * BST;
        const float* Bl = Bh + 16 * BST;
#pragma unroll
        for (int ks = 0; ks < 2; ks++) {
            const int kc = ks * 8 + (lane & 3);
            unsigned ah[2][4], al[2][4], bh[4][2], bl[4][2];
#pragma unroll
            for (int im = 0; im < 2; im++) {
                int mr = wm * 32 + im * 16 + (lane >> 2);
                ah[im][0] = __float_as_uint(Ah[kc * AST + mr]);
                ah[im][1] = __float_as_uint(Ah[kc * AST + mr + 8]);
                ah[im][2] = __float_as_uint(Ah[(kc + 4) * AST + mr]);
                ah[im][3] = __float_as_uint(Ah[(kc + 4) * AST + mr + 8]);
                al[im][0] = __float_as_uint(Al[kc * AST + mr]);
                al[im][1] = __float_as_uint(Al[kc * AST + mr + 8]);
                al[im][2] = __float_as_uint(Al[(kc + 4) * AST + mr]);
                al[im][3] = __float_as_uint(Al[(kc + 4) * AST + mr + 8]);
            }
#pragma unroll
            for (int jn = 0; jn < 4; jn++) {
                int nc = wn * 32 + jn * 8 + (lane >> 2);
                bh[jn][0] = __float_as_uint(Bh[kc * BST + nc]);
                bh[jn][1] = __float_as_uint(Bh[(kc + 4) * BST + nc]);
                bl[jn][0] = __float_as_uint(Bl[kc * BST + nc]);
                bl[jn][1] = __float_as_uint(Bl[(kc + 4) * BST + nc]);
            }
#pragma unroll
            for (int im = 0; im < 2; im++)
#pragma unroll
                for (int jn = 0; jn < 4; jn++) {
                    MMA_TF32(acc[im][jn], ah[im], bh[jn]);
                    MMA_TF32(acc[im][jn], ah[im], bl[jn]);
                    MMA_TF32(acc[im][jn], al[im], bh[jn]);
                }
        }
    };

    loadRegs(0);
    storeSmem(0);
    __syncthreads();
    for (int c = 0; c < nchunks; c++) {
        int cur = c & 1;
        bool more = (c + 1 < nchunks);
        if (more) loadRegs(c + 1);
        compute(cur);
        if (more) { __syncthreads(); storeSmem(cur ^ 1); __syncthreads(); }
    }
    __syncthreads();

#pragma unroll
    for (int im = 0; im < 2; im++)
#pragma unroll
        for (int jn = 0; jn < 4; jn++) {
            int r = wm * 32 + im * 16 + (lane >> 2);
            int c2 = wn * 32 + jn * 8 + (lane & 3) * 2;
            Cs[r * 65 + c2]           = acc[im][jn][0];
            Cs[r * 65 + c2 + 1]       = acc[im][jn][1];
            Cs[(r + 8) * 65 + c2]     = acc[im][jn][2];
            Cs[(r + 8) * 65 + c2 + 1] = acc[im][jn][3];
        }
    __syncthreads();

#pragma unroll
    for (int it = 0; it < 32; it++) {
        int e = tid + it * 256;
        int b  = e & 63;
        int n  = (e >> 6) & 63;
        int tt = e >> 12;
        float v = Cs[(tt * 64 + b) * 65 + n] + __ldg(bias + (size_t)dg * H_ + n0 + n);
        g_gx[(((size_t)(t0 + tt) * 8 + dg) * H_ + n0 + n) * B_ + b] = v;
    }

    // publish readiness for this t-pair (64 contributions = ready)
    __syncthreads();
    if (tid == 0) {
        __threadfence();
        atomicAdd(&g_gx_ready[t0 >> 1], 1u);
    }
}

// ---------------- persistent scan: bf16-split MMA, waits on per-t gx flags ----------------
__global__ __launch_bounds__(512, 1) void scan_kernel(
    const float* __restrict__ w_hh,       // [2][4][H][H]  ([d][g][j][h])
    const float* __restrict__ b_hh,       // [2][4][H]
    const float* __restrict__ noise_hid,  // [2][4][B][H]
    const float* __restrict__ mask,       // [T][B]
    int layer, float* __restrict__ out)
{
    extern __shared__ __align__(16) char smraw[];
    unsigned*       Wp    = (unsigned*)smraw;                       // 131072 B
    unsigned short* wbufs = (unsigned short*)(smraw + 131072);      // 65536 B
    float*          gBuf  = (float*)(smraw + 196608);               // 16384 B
    float*          gxBuf = (float*)(smraw + 212992);               // 16384 B
    unsigned*       sHi32 = (unsigned*)(smraw + 131072);            // 8192 B (reuse wbufs)
    unsigned*       sLo32 = (unsigned*)(smraw + 131072 + 8192);     // 8192 B
    float*          sOut  = (float*)(smraw + 131072 + 16384);       // 5120 B

    const int tid  = threadIdx.x;
    const int d    = blockIdx.x >> 5;
    const int h0   = (blockIdx.x & 31) * HT;
    const int w    = tid >> 5;
    const int lane = tid & 31;
    const int g    = w >> 2;
    const int q    = w & 3;
    const int gid  = lane >> 2;
    const int c2   = lane & 3;
    const int b0w  = q * 16;

    // ---- prepack W fragments (once) ----
    for (int i = tid; i < 4096; i += 512) {
        int gg = i >> 10, ks = (i >> 5) & 31, ln = i & 31;
        int gd = ln >> 2, cc = ln & 3;
        int j0 = ks * 16 + cc * 2;
        const float* Wb = w_hh + ((size_t)(d * 4 + gg) * H_) * H_;
        unsigned rh[4], rl[4];
#pragma unroll
        for (int r = 0; r < 4; r++) {
            int j = j0 + (r >> 1) * 8;
            int h = h0 + gd + (r & 1) * 8;
            float w0 = Wb[(size_t)j * H_ + h];
            float w1 = Wb[(size_t)(j + 1) * H_ + h];
            __nv_bfloat16 h0b = __float2bfloat16(w0);
            __nv_bfloat16 h1b = __float2bfloat16(w1);
            __nv_bfloat16 l0b = __float2bfloat16(w0 - __bfloat162float(h0b));
            __nv_bfloat16 l1b = __float2bfloat16(w1 - __bfloat162float(h1b));
            rh[r] = (unsigned)__bfloat16_as_ushort(h0b) | ((unsigned)__bfloat16_as_ushort(h1b) << 16);
            rl[r] = (unsigned)__bfloat16_as_ushort(l0b) | ((unsigned)__bfloat16_as_ushort(l1b) << 16);
        }
        unsigned* ph = Wp + ((size_t)((0 * 4 + gg) * 32 + ks) * 32 + ln) * 4;
        unsigned* pl = Wp + ((size_t)((1 * 4 + gg) * 32 + ks) * 32 + ln) * 4;
#pragma unroll
        for (int r = 0; r < 4; r++) { ph[r] = rh[r]; pl[r] = rl[r]; }
    }

    // pointwise side: 2 adjacent cells per thread: (b, h0 + hp*2 + k)
    const int b  = tid & 63;
    const int hp = tid >> 6;            // 0..7
    float bh[2][4], nz[2][4];
#pragma unroll
    for (int k = 0; k < 2; k++) {
        int hl = hp * 2 + k;
#pragma unroll
        for (int gg = 0; gg < 4; gg++) {
            bh[k][gg] = b_hh[(size_t)(d * 4 + gg) * H_ + h0 + hl];
            nz[k][gg] = noise_hid[((size_t)(d * 4 + gg) * B_ + b) * H_ + h0 + hl];
        }
    }
    float hreg[2] = {0.f, 0.f}, creg[2] = {0.f, 0.f};
    float* outp = layer ? out : g_hs0;

    unsigned short* wb = wbufs + (size_t)w * 2048;   // per-warp buffer (4096 B)
    const size_t rowbase = (size_t)(d * 4 + g) * B_;

    __syncthreads();

    for (int s = 0; s < T_; s++) {
        const int t = d ? (T_ - 1 - s) : s;
        const unsigned short* hi_in = g_hnhi[s & 1];
        const unsigned short* lo_in = g_hnlo[s & 1];
        unsigned short* hi_out = g_hnhi[(s + 1) & 1];
        unsigned short* lo_out = g_hnlo[(s + 1) & 1];

        // ---- wait for gx of this t to be published (concurrent gx kernel) ----
        if (tid == 0) {
            unsigned v;
            const unsigned* fp = g_gx_ready + (t >> 1);
            do {
                asm volatile("ld.acquire.gpu.u32 %0, [%1];" : "=r"(v) : "l"(fp) : "memory");
            } while (v < 64u);
        }
        __syncthreads();

        // ---- gx prefetch (16 KB) -> gxBuf, overlapped with GEMM ----
        {
            const float* gsrc = g_gx + ((size_t)t * 8 + d * 4) * (size_t)(H_ * B_) + (size_t)h0 * B_;
#pragma unroll
            for (int i = 0; i < 2; i++) {
                int e = tid + i * 512;           // 0..1023
                int gg = e >> 8, hh = (e >> 4) & 15, sg = e & 15;
                cp_async16(gxBuf + (gg * 16 + hh) * 64 + sg * 4,
                           gsrc + (size_t)gg * (H_ * B_) + (size_t)hh * B_ + sg * 4);
            }
            CP_COMMIT();
        }

        float acc[2][4] = {};

        auto prefetch = [&](int c, int bf) {
#pragma unroll
            for (int it = 0; it < 2; it++) {
                int item = lane + it * 32;
                int r = item >> 2, seg = item & 3;
                size_t gsrc = (rowbase + b0w + r) * H_ + c * JCS + seg * 8;
                cp_async16(wb + ((bf * 2 + 0) * 16 + r) * JPAD + seg * 8, hi_in + gsrc);
                cp_async16(wb + ((bf * 2 + 1) * 16 + r) * JPAD + seg * 8, lo_in + gsrc);
            }
        };

        prefetch(0, 0);
        CP_COMMIT();

        for (int c = 0; c < NCH; c++) {
            if (c + 1 < NCH) {
                prefetch(c + 1, (c + 1) & 1);
                CP_COMMIT();
                CP_WAIT1();
            } else {
                CP_WAIT0();
            }
            __syncwarp();

            const unsigned short* bufh = wb + (((c & 1) * 2 + 0) * 16) * JPAD;
            const unsigned short* bufl = wb + (((c & 1) * 2 + 1) * 16) * JPAD;
#pragma unroll
            for (int ksl = 0; ksl < 2; ksl++) {
                int gk = c * 2 + ksl;
                int j0 = ksl * 16 + c2 * 2;
                uint4 ahi = *(const uint4*)(Wp + ((size_t)((0 * 4 + g) * 32 + gk) * 32 + lane) * 4);
                uint4 alo = *(const uint4*)(Wp + ((size_t)((1 * 4 + g) * 32 + gk) * 32 + lane) * 4);
#pragma unroll
                for (int nt = 0; nt < 2; nt++) {
                    int row = nt * 8 + gid;
                    unsigned bh0 = *(const unsigned*)(bufh + row * JPAD + j0);
                    unsigned bh1 = *(const unsigned*)(bufh + row * JPAD + j0 + 8);
                    unsigned bl0 = *(const unsigned*)(bufl + row * JPAD + j0);
                    unsigned bl1 = *(const unsigned*)(bufl + row * JPAD + j0 + 8);
                    MMA_BF16(acc[nt], ahi, bh0, bh1);
                    MMA_BF16(acc[nt], ahi, bl0, bl1);
                    MMA_BF16(acc[nt], alo, bh0, bh1);
                }
            }
            __syncwarp();
        }

        // ---- gate exchange ----
#pragma unroll
        for (int nt = 0; nt < 2; nt++) {
            int bb = b0w + nt * 8 + c2 * 2;
            gBuf[(g * 16 + gid) * 64 + bb]         = acc[nt][0];
            gBuf[(g * 16 + gid) * 64 + bb + 1]     = acc[nt][1];
            gBuf[(g * 16 + gid + 8) * 64 + bb]     = acc[nt][2];
            gBuf[(g * 16 + gid + 8) * 64 + bb + 1] = acc[nt][3];
        }
        __syncthreads();   // S1: GEMM + exchange complete; wbufs free; gxBuf ready

        // ---- LSTM pointwise: 2 adjacent cells per thread ----
        const float mt = mask[(size_t)t * B_ + b];
#pragma unroll
        for (int k = 0; k < 2; k++) {
            int hl = hp * 2 + k;
            float x0 = gBuf[(0 * 16 + hl) * 64 + b] + gxBuf[(0 * 16 + hl) * 64 + b] + bh[k][0];
            float x1 = gBuf[(1 * 16 + hl) * 64 + b] + gxBuf[(1 * 16 + hl) * 64 + b] + bh[k][1];
            float x2 = gBuf[(2 * 16 + hl) * 64 + b] + gxBuf[(2 * 16 + hl) * 64 + b] + bh[k][2];
            float x3 = gBuf[(3 * 16 + hl) * 64 + b] + gxBuf[(3 * 16 + hl) * 64 + b] + bh[k][3];

            float ig = 1.f / (1.f + __expf(-x0));
            float fg = 1.f / (1.f + __expf(-x1));
            float gt = tanhf(x2);
            float og = 1.f / (1.f + __expf(-x3));

            float cn = fg * creg[k] + ig * gt;
            float hv = og * tanhf(cn);
            hreg[k] = hv * mt + hreg[k] * (1.f - mt);
            creg[k] = cn * mt + creg[k] * (1.f - mt);

            if (s == T_ - 1) {
                size_t si = ((size_t)d * B_ + b) * H_ + h0 + hl;
                g_h[layer][si] = hreg[k];
                g_c[layer][si] = creg[k];
            }
        }

        // stage hn (packed u32 per j-pair) + output h into smem
#pragma unroll
        for (int gg = 0; gg < 4; gg++) {
            float v0 = hreg[0] * nz[0][gg];
            float v1 = hreg[1] * nz[1][gg];
            __nv_bfloat16 h0b = __float2bfloat16(v0);
            __nv_bfloat16 h1b = __float2bfloat16(v1);
            __nv_bfloat16 l0b = __float2bfloat16(v0 - __bfloat162float(h0b));
            __nv_bfloat16 l1b = __float2bfloat16(v1 - __bfloat162float(h1b));
            sHi32[(gg * 64 + b) * 8 + hp] =
                (unsigned)__bfloat16_as_ushort(h0b) | ((unsigned)__bfloat16_as_ushort(h1b) << 16);
            sLo32[(gg * 64 + b) * 8 + hp] =
                (unsigned)__bfloat16_as_ushort(l0b) | ((unsigned)__bfloat16_as_ushort(l1b) << 16);
        }
        sOut[b * 20 + hp * 2 + 0] = hreg[0];
        sOut[b * 20 + hp * 2 + 1] = hreg[1];
        __syncthreads();   // S2: stages complete

        // ---- cooperative coalesced hn stores ----
        {
            unsigned* ghi = (unsigned*)hi_out;
            unsigned* glo = (unsigned*)lo_out;
#pragma unroll
            for (int i = 0; i < 4; i++) {
                int e = tid + i * 512;           // 0..2047
                int gg = e >> 9, bb = (e >> 3) & 63, p = e & 7;
                size_t gi = ((size_t)(d * 4 + gg) * B_ + bb) * (H_ / 2) + (h0 >> 1) + p;
                ghi[gi] = sHi32[e];
                glo[gi] = sLo32[e];
            }
        }
        __syncthreads();   // S3: hn stores issued block-wide

        if (tid == 0) {
            __threadfence();
            unsigned a = atomicAdd(&g_bar_cnt, 1u);
            if (a == (unsigned)(NBLK_S * (s + 1)) - 1u) {
                asm volatile("st.release.gpu.u32 [%0], %1;" :: "l"(&g_bar_gen), "r"((unsigned)(s + 1)) : "memory");
            } else {
                unsigned v;
                do {
                    asm volatile("ld.acquire.gpu.u32 %0, [%1];" : "=r"(v) : "l"(&g_bar_gen) : "memory");
                } while (v < (unsigned)(s + 1));
            }
        } else if (tid >= 256) {
            // output stores overlapped with tid0's barrier spin (no cross-block consumer)
            int e = tid - 256;
            int bb = e >> 2, qq = e & 3;
            float4 v = *(const float4*)&sOut[bb * 20 + qq * 4];
            *(float4*)(outp + ((size_t)t * B_ + bb) * (2 * H_) + (size_t)d * H_ + h0 + qq * 4) = v;
        }
        __syncthreads();   // S4: barrier released; safe to touch wbufs/gxBuf next step
    }
}

// ---------------- finalize ----------------
__global__ void final_kernel(float* __restrict__ out) {
    int i = blockIdx.x * blockDim.x + threadIdx.x;
    if (i >= 4 * B_ * H_) return;
    int l = i >> 16;
    int r = i & 65535;
    size_t O = (size_t)T_ * B_ * 2 * H_;
    out[O + i]          = g_h[l][r];
    out[O + 131072 + i] = g_c[l][r];
}

// ---------------- launch ----------------
extern "C" void kernel_launch(void* const* d_in, const int* in_sizes, int n_in,
                              void* d_out, int out_size) {
    const float* x            = (const float*)d_in[0];
    const float* mask         = (const float*)d_in[1];
    const float* w_ih_l0      = (const float*)d_in[2];
    const float* w_hh_l0      = (const float*)d_in[3];
    const float* b_ih_l0      = (const float*)d_in[4];
    const float* b_hh_l0      = (const float*)d_in[5];
    const float* noise_in_l0  = (const float*)d_in[6];
    const float* noise_hid_l0 = (const float*)d_in[7];
    const float* w_ih_l1      = (const float*)d_in[8];
    const float* w_hh_l1      = (const float*)d_in[9];
    const float* b_ih_l1      = (const float*)d_in[10];
    const float* b_hh_l1      = (const float*)d_in[11];
    const float* noise_in_l1  = (const float*)d_in[12];
    const float* noise_hid_l1 = (const float*)d_in[13];
    float* out = (float*)d_out;

    const int SCAN_SMEM = 131072 + 65536 + 16384 + 16384;               // 229376 B
    cudaFuncSetAttribute(scan_kernel, cudaFuncAttributeMaxDynamicSharedMemorySize, SCAN_SMEM);
    const int GX_SMEM = (4 * 16 * AST + 4 * 16 * BST) * sizeof(float);  // 51200 B
    cudaFuncSetAttribute(gx_tf32_kernel, cudaFuncAttributeMaxDynamicSharedMemorySize, GX_SMEM);

    // side stream + events, created fresh each call (host objects only; not captured ops)
    cudaStream_t sB;
    cudaStreamCreateWithFlags(&sB, cudaStreamNonBlocking);
    cudaEvent_t evA, evB, evC, evD;
    cudaEventCreateWithFlags(&evA, cudaEventDisableTiming);
    cudaEventCreateWithFlags(&evB, cudaEventDisableTiming);
    cudaEventCreateWithFlags(&evC, cudaEventDisableTiming);
    cudaEventCreateWithFlags(&evD, cudaEventDisableTiming);

    dim3 gxGrid(64, 128, 1);

    // ----- layer 0: gx on side stream, scan (flag-synced) concurrent on main -----
    init_kernel<<<512, 512>>>(0);
    cudaEventRecord(evA, 0);
    cudaStreamWaitEvent(sB, evA, 0);
    gx_tf32_kernel<<<gxGrid, 256, GX_SMEM, sB>>>(x, noise_in_l0, w_ih_l0, b_ih_l0, IN_, 0);
    cudaEventRecord(evB, sB);
    scan_kernel<<<NBLK_S, 512, SCAN_SMEM>>>(w_hh_l0, b_hh_l0, noise_hid_l0, mask, 0, out);

    // ----- layer 1 -----
    cudaStreamWaitEvent(0, evB, 0);            // gx0 done before flags reset
    init_kernel<<<512, 512>>>(1);
    cudaEventRecord(evC, 0);
    cudaStreamWaitEvent(sB, evC, 0);
    gx_tf32_kernel<<<gxGrid, 256, GX_SMEM, sB>>>(nullptr, noise_in_l1, w_ih_l1, b_ih_l1, 2 * H_, 1);
    cudaEventRecord(evD, sB);
    scan_kernel<<<NBLK_S, 512, SCAN_SMEM>>>(w_hh_l1, b_hh_l1, noise_hid_l1, mask, 1, out);

    cudaStreamWaitEvent(0, evD, 0);            // rejoin side stream before capture ends
    final_kernel<<<256, 512>>>(out);
}

// round 17
// speedup vs baseline: 1.6363x; 1.0156x over previous
#include <cuda_runtime.h>
#include <cuda_bf16.h>
#include <math.h>

#define T_  256
#define B_  64
#define IN_ 512
#define H_  512

// ---- scan config ----
#define HT     16                 // h per block
#define NBLK_S 64                 // 2 dirs x 32 h-tiles
#define JCS    32                 // j per chunk
#define NCH    (H_ / JCS)         // 16 chunks

// ---------------- scratch (device globals; no allocation allowed) ----------------
__device__ float  g_gx [(size_t)T_ * 8 * H_ * B_];   // [t][dg][h][b]
__device__ float  g_hs0[(size_t)T_ * B_ * 2 * H_];   // layer-0 output [t][b][d*H+h]
__device__ float  g_h  [2][2 * B_ * H_];
__device__ float  g_c  [2][2 * B_ * H_];
// hn planes, bulk-copy friendly layout: [dg(8)][jc(16)][b(64)][jw(32)] ushort
__device__ unsigned short g_hnhi[2][2 * 4 * B_ * H_];
__device__ unsigned short g_hnlo[2][2 * 4 * B_ * H_];
__device__ unsigned g_bar_cnt;
__device__ unsigned g_bar_gen;
__device__ unsigned g_gx_ready[T_ / 2];              // per t-pair completion count (64 = ready)

// ---------------- helpers ----------------
__device__ __forceinline__ unsigned f2tf32(float x) {
    unsigned r; asm("cvt.rna.tf32.f32 %0, %1;" : "=r"(r) : "f"(x)); return r;
}
__device__ __forceinline__ void bulk_g2s(unsigned dst_sh, const void* src, unsigned bytes, unsigned mbar_sh) {
    asm volatile("cp.async.bulk.shared::cluster.global.mbarrier::complete_tx::bytes [%0], [%1], %2, [%3];"
        :: "r"(dst_sh), "l"(src), "r"(bytes), "r"(mbar_sh) : "memory");
}
__device__ __forceinline__ void mbar_expect(unsigned mbar_sh, unsigned bytes) {
    asm volatile("mbarrier.arrive.expect_tx.shared.b64 _, [%0], %1;" :: "r"(mbar_sh), "r"(bytes) : "memory");
}
__device__ __forceinline__ void mbar_wait(unsigned mbar_sh, unsigned parity) {
    asm volatile(
        "{\n\t.reg .pred P;\n\t"
        "MWL%=:\n\t"
        "mbarrier.try_wait.parity.acquire.cta.shared::cta.b64 P, [%0], %1, 0x989680;\n\t"
        "@P bra MWD%=;\n\t"
        "bra MWL%=;\n\t"
        "MWD%=:\n\t}"
        :: "r"(mbar_sh), "r"(parity) : "memory");
}

#define MMA_TF32(c, a, b) asm volatile( \
    "mma.sync.aligned.m16n8k8.row.col.f32.tf32.tf32.f32 " \
    "{%0,%1,%2,%3}, {%4,%5,%6,%7}, {%8,%9}, {%0,%1,%2,%3};" \
    : "+f"((c)[0]), "+f"((c)[1]), "+f"((c)[2]), "+f"((c)[3]) \
    : "r"((a)[0]), "r"((a)[1]), "r"((a)[2]), "r"((a)[3]), \
      "r"((b)[0]), "r"((b)[1]))

#define MMA_BF16(c, a, b0v, b1v) asm volatile( \
    "mma.sync.aligned.m16n8k16.row.col.f32.bf16.bf16.f32 " \
    "{%0,%1,%2,%3}, {%4,%5,%6,%7}, {%8,%9}, {%0,%1,%2,%3};" \
    : "+f"((c)[0]), "+f"((c)[1]), "+f"((c)[2]), "+f"((c)[3]) \
    : "r"((a).x), "r"((a).y), "r"((a).z), "r"((a).w), \
      "r"(b0v), "r"(b1v))

// ---------------- init ----------------
__global__ void init_kernel(int layer) {
    int i = blockIdx.x * blockDim.x + threadIdx.x;   // 262144 threads
    if (i < 2 * B_ * H_) { g_h[layer][i] = 0.f; g_c[layer][i] = 0.f; }
    if (i < 2 * 4 * B_ * H_) { g_hnhi[0][i] = 0; g_hnlo[0][i] = 0; }
    if (i < T_ / 2) g_gx_ready[i] = 0;
    if (i == 0) { g_bar_cnt = 0; g_bar_gen = 0; }
}

// ---------------- gx GEMM via 3xTF32 tensor cores (unchanged from R13) ----------------
#define AST 132
#define BST 68
__global__ __launch_bounds__(256, 2) void gx_tf32_kernel(
    const float* __restrict__ X,
    const float* __restrict__ noise,
    const float* __restrict__ W,
    const float* __restrict__ bias,
    int K, int layer)
{
    extern __shared__ __align__(16) float sm[];
    float* smA = sm;
    float* smB = sm + 4 * 16 * AST;
    float* Cs  = sm;

    const int nt = blockIdx.x & 7;
    const int dg = blockIdx.x >> 3;
    const int n0 = nt * 64;
    const int z  = blockIdx.y;
    const int zi = z >> 1;
    const int t0 = (z & 1) ? (T_ - 2 - 2 * zi) : (2 * zi);
    const int m0 = t0 * 64;

    const int tid = threadIdx.x;
    const int lane = tid & 31;
    const int warp = tid >> 5;
    const int wm = warp & 3;
    const int wn = warp >> 2;

    const int m_l = tid >> 1;
    const int kq  = (tid & 1) * 8;
    const int k_l = tid >> 4;
    const int n4  = (tid & 15) * 4;

    const float* Xsrc = layer ? g_hs0 : X;
    const float* xrow = Xsrc + (size_t)(m0 + m_l) * K;
    const float* nrow = noise + ((size_t)dg * B_ + ((m0 + m_l) & 63)) * K;
    const float* Wg   = W + (size_t)dg * K * H_;

    unsigned ahi[8], alo[8], bhi[4], blo[4];
    float acc[2][4][4] = {};

    const int nchunks = K >> 4;

    auto loadRegs = [&](int c) {
        int k0 = c * 16;
#pragma unroll
        for (int j = 0; j < 2; j++) {
            float4 xv = *(const float4*)(xrow + k0 + kq + j * 4);
            float4 nv = *(const float4*)(nrow + k0 + kq + j * 4);
            float p[4] = { xv.x * nv.x, xv.y * nv.y, xv.z * nv.z, xv.w * nv.w };
#pragma unroll
            for (int i = 0; i < 4; i++) {
                unsigned h = f2tf32(p[i]);
                ahi[j * 4 + i] = h;
                alo[j * 4 + i] = f2tf32(p[i] - __uint_as_float(h));
            }
        }
        float4 wv = *(const float4*)(Wg + (size_t)(k0 + k_l) * H_ + n0 + n4);
        float q[4] = { wv.x, wv.y, wv.z, wv.w };
#pragma unroll
        for (int i = 0; i < 4; i++) {
            unsigned h = f2tf32(q[i]);
            bhi[i] = h;
            blo[i] = f2tf32(q[i] - __uint_as_float(h));
        }
    };

    auto storeSmem = [&](int buf) {
        float* Ah = smA + buf * 2 * 16 * AST;
        float* Al = Ah + 16 * AST;
#pragma unroll
        for (int j = 0; j < 2; j++)
#pragma unroll
            for (int i = 0; i < 4; i++) {
                Ah[(kq + j * 4 + i) * AST + m_l] = __uint_as_float(ahi[j * 4 + i]);
                Al[(kq + j * 4 + i) * AST + m_l] = __uint_as_float(alo[j * 4 + i]);
            }
        float* Bh = smB + buf * 2 * 16 * BST;
        float* Bl = Bh + 16 * BST;
#pragma unroll
        for (int i = 0; i < 4; i++) {
            Bh[k_l * BST + n4 + i] = __uint_as_float(bhi[i]);
            Bl[k_l * BST + n4 + i] = __uint_as_float(blo[i]);
        }
    };

    auto compute = [&](int buf) {
        const float* Ah = smA + buf * 2 * 16 * AST;
        const float* Al = Ah + 16 * AST;
        const float* Bh = smB + buf * 2 * 16 * BST;
        const float* Bl = Bh + 16 * BST;
#pragma unroll
        for (int ks = 0; ks < 2; ks++) {
            const int kc = ks * 8 + (lane & 3);
            unsigned ah[2][4], al[2][4], bh[4][2], bl[4][2];
#pragma unroll
            for (int im = 0; im < 2; im++) {
                int mr = wm * 32 + im * 16 + (lane >> 2);
                ah[im][0] = __float_as_uint(Ah[kc * AST + mr]);
                ah[im][1] = __float_as_uint(Ah[kc * AST + mr + 8]);
                ah[im][2] = __float_as_uint(Ah[(kc + 4) * AST + mr]);
                ah[im][3] = __float_as_uint(Ah[(kc + 4) * AST + mr + 8]);
                al[im][0] = __float_as_uint(Al[kc * AST + mr]);
                al[im][1] = __float_as_uint(Al[kc * AST + mr + 8]);
                al[im][2] = __float_as_uint(Al[(kc + 4) * AST + mr]);
                al[im][3] = __float_as_uint(Al[(kc + 4) * AST + mr + 8]);
            }
#pragma unroll
            for (int jn = 0; jn < 4; jn++) {
                int nc = wn * 32 + jn * 8 + (lane >> 2);
                bh[jn][0] = __float_as_uint(Bh[kc * BST + nc]);
                bh[jn][1] = __float_as_uint(Bh[(kc + 4) * BST + nc]);
                bl[jn][0] = __float_as_uint(Bl[kc * BST + nc]);
                bl[jn][1] = __float_as_uint(Bl[(kc + 4) * BST + nc]);
            }
#pragma unroll
            for (int im = 0; im < 2; im++)
#pragma unroll
                for (int jn = 0; jn < 4; jn++) {
                    MMA_TF32(acc[im][jn], ah[im], bh[jn]);
                    MMA_TF32(acc[im][jn], ah[im], bl[jn]);
                    MMA_TF32(acc[im][jn], al[im], bh[jn]);
                }
        }
    };

    loadRegs(0);
    storeSmem(0);
    __syncthreads();
    for (int c = 0; c < nchunks; c++) {
        int cur = c & 1;
        bool more = (c + 1 < nchunks);
        if (more) loadRegs(c + 1);
        compute(cur);
        if (more) { __syncthreads(); storeSmem(cur ^ 1); __syncthreads(); }
    }
    __syncthreads();

#pragma unroll
    for (int im = 0; im < 2; im++)
#pragma unroll
        for (int jn = 0; jn < 4; jn++) {
            int r = wm * 32 + im * 16 + (lane >> 2);
            int c2 = wn * 32 + jn * 8 + (lane & 3) * 2;
            Cs[r * 65 + c2]           = acc[im][jn][0];
            Cs[r * 65 + c2 + 1]       = acc[im][jn][1];
            Cs[(r + 8) * 65 + c2]     = acc[im][jn][2];
            Cs[(r + 8) * 65 + c2 + 1] = acc[im][jn][3];
        }
    __syncthreads();

#pragma unroll
    for (int it = 0; it < 32; it++) {
        int e = tid + it * 256;
        int b  = e & 63;
        int n  = (e >> 6) & 63;
        int tt = e >> 12;
        float v = Cs[(tt * 64 + b) * 65 + n] + __ldg(bias + (size_t)dg * H_ + n0 + n);
        g_gx[(((size_t)(t0 + tt) * 8 + dg) * H_ + n0 + n) * B_ + b] = v;
    }

    __syncthreads();
    if (tid == 0) {
        __threadfence();
        atomicAdd(&g_gx_ready[t0 >> 1], 1u);
    }
}

// ---------------- persistent scan: bf16-split MMA, cp.async.bulk loads ----------------
// smem map (bytes): Wp 0..131072 | wbufs 131072..196608 (16 warps x 4096)
//                   gBuf 196608..212992 | gxBuf 212992..229376 | mbars 229376..229888
// wbufs region reused post-GEMM as sHi32/sLo32/sOut staging.
__global__ __launch_bounds__(512, 1) void scan_kernel(
    const float* __restrict__ w_hh,       // [2][4][H][H]  ([d][g][j][h])
    const float* __restrict__ b_hh,       // [2][4][H]
    const float* __restrict__ noise_hid,  // [2][4][B][H]
    const float* __restrict__ mask,       // [T][B]
    int layer, float* __restrict__ out)
{
    extern __shared__ __align__(16) char smraw[];
    unsigned*       Wp    = (unsigned*)smraw;
    unsigned short* wbufs = (unsigned short*)(smraw + 131072);
    float*          gBuf  = (float*)(smraw + 196608);
    float*          gxBuf = (float*)(smraw + 212992);
    unsigned*       sHi32 = (unsigned*)(smraw + 131072);
    unsigned*       sLo32 = (unsigned*)(smraw + 131072 + 8192);
    float*          sOut  = (float*)(smraw + 131072 + 16384);

    const int tid  = threadIdx.x;
    const int d    = blockIdx.x >> 5;
    const int h0   = (blockIdx.x & 31) * HT;
    const int w    = tid >> 5;
    const int lane = tid & 31;
    const int g    = w >> 2;
    const int q    = w & 3;
    const int gid  = lane >> 2;
    const int c2   = lane & 3;
    const int b0w  = q * 16;
    const int dg16 = (d * 4 + g) * 16;

    const unsigned smem_base = (unsigned)__cvta_generic_to_shared(smraw);
    const unsigned wb_sh   = smem_base + 131072 + w * 4096;
    const unsigned mb_sh   = smem_base + 229376 + w * 16;     // 2 per-warp mbarriers
    const unsigned gxmb_sh = smem_base + 229376 + 256;        // block mbarrier
    const unsigned gx_sh   = smem_base + 212992;

    // ---- mbarrier init ----
    if (lane == 0) {
        asm volatile("mbarrier.init.shared.b64 [%0], 1;" :: "r"(mb_sh) : "memory");
        asm volatile("mbarrier.init.shared.b64 [%0], 1;" :: "r"(mb_sh + 8) : "memory");
    }
    if (tid == 0)
        asm volatile("mbarrier.init.shared.b64 [%0], 1;" :: "r"(gxmb_sh) : "memory");
    asm volatile("fence.proxy.async.shared::cta;" ::: "memory");

    // ---- prepack W fragments (once) ----
    for (int i = tid; i < 4096; i += 512) {
        int gg = i >> 10, ks = (i >> 5) & 31, ln = i & 31;
        int gd = ln >> 2, cc = ln & 3;
        int j0 = ks * 16 + cc * 2;
        const float* Wb = w_hh + ((size_t)(d * 4 + gg) * H_) * H_;
        unsigned rh[4], rl[4];
#pragma unroll
        for (int r = 0; r < 4; r++) {
            int j = j0 + (r >> 1) * 8;
            int h = h0 + gd + (r & 1) * 8;
            float w0 = Wb[(size_t)j * H_ + h];
            float w1 = Wb[(size_t)(j + 1) * H_ + h];
            __nv_bfloat16 h0b = __float2bfloat16(w0);
            __nv_bfloat16 h1b = __float2bfloat16(w1);
            __nv_bfloat16 l0b = __float2bfloat16(w0 - __bfloat162float(h0b));
            __nv_bfloat16 l1b = __float2bfloat16(w1 - __bfloat162float(h1b));
            rh[r] = (unsigned)__bfloat16_as_ushort(h0b) | ((unsigned)__bfloat16_as_ushort(h1b) << 16);
            rl[r] = (unsigned)__bfloat16_as_ushort(l0b) | ((unsigned)__bfloat16_as_ushort(l1b) << 16);
        }
        unsigned* ph = Wp + ((size_t)((0 * 4 + gg) * 32 + ks) * 32 + ln) * 4;
        unsigned* pl = Wp + ((size_t)((1 * 4 + gg) * 32 + ks) * 32 + ln) * 4;
#pragma unroll
        for (int r = 0; r < 4; r++) { ph[r] = rh[r]; pl[r] = rl[r]; }
    }

    // pointwise side: 2 adjacent cells per thread: (b, h0 + hp*2 + k)
    const int b  = tid & 63;
    const int hp = tid >> 6;            // 0..7
    float bh[2][4], nz[2][4];
#pragma unroll
    for (int k = 0; k < 2; k++) {
        int hl = hp * 2 + k;
#pragma unroll
        for (int gg = 0; gg < 4; gg++) {
            bh[k][gg] = b_hh[(size_t)(d * 4 + gg) * H_ + h0 + hl];
            nz[k][gg] = noise_hid[((size_t)(d * 4 + gg) * B_ + b) * H_ + h0 + hl];
        }
    }
    float hreg[2] = {0.f, 0.f}, creg[2] = {0.f, 0.f};
    float* outp = layer ? out : g_hs0;

    const int jcB = h0 >> 5;            // producer-side jc of this block
    const int jpb = (h0 & 31) >> 1;     // pair offset within jc

    unsigned phb[2] = {0u, 0u};
    unsigned phg = 0u;

    __syncthreads();

    for (int s = 0; s < T_; s++) {
        const int t = d ? (T_ - 1 - s) : s;
        const unsigned short* hi_in = g_hnhi[s & 1];
        const unsigned short* lo_in = g_hnlo[s & 1];
        unsigned short* hi_out = g_hnhi[(s + 1) & 1];
        unsigned short* lo_out = g_hnlo[(s + 1) & 1];

        auto issue_chunk = [&](int c, int bf) {
            if (lane == 0) {
                unsigned mb = mb_sh + bf * 8;
                mbar_expect(mb, 2048);
                const void* sh = hi_in + ((size_t)(dg16 + c) * 64 + b0w) * 32;
                const void* sl = lo_in + ((size_t)(dg16 + c) * 64 + b0w) * 32;
                bulk_g2s(wb_sh + bf * 2048,        sh, 1024, mb);
                bulk_g2s(wb_sh + bf * 2048 + 1024, sl, 1024, mb);
            }
        };

        // prefetch chunks 0,1 immediately (hn ready via grid barrier of step s-1)
        issue_chunk(0, 0);
        issue_chunk(1, 1);

        // tid0: wait for gx of this t, then issue gx bulk copies
        if (tid == 0) {
            unsigned v;
            const unsigned* fp = g_gx_ready + (t >> 1);
            do {
                asm volatile("ld.acquire.gpu.u32 %0, [%1];" : "=r"(v) : "l"(fp) : "memory");
            } while (v < 64u);
            mbar_expect(gxmb_sh, 16384);
            const float* gsrc = g_gx + ((size_t)t * 8 + d * 4) * (size_t)(H_ * B_) + (size_t)h0 * B_;
#pragma unroll
            for (int gg = 0; gg < 4; gg++)
                bulk_g2s(gx_sh + gg * 4096, gsrc + (size_t)gg * (H_ * B_), 4096, gxmb_sh);
        }

        // ---- GEMM over 16 chunks, per-warp double-buffered bulk pipeline ----
        float acc[2][4] = {};
        for (int c = 0; c < NCH; c++) {
            int bf = c & 1;
            mbar_wait(mb_sh + bf * 8, phb[bf]);
            phb[bf] ^= 1;

            const unsigned short* bufh = wbufs + (size_t)w * 2048 + bf * 1024;
            const unsigned short* bufl = bufh + 512;
#pragma unroll
            for (int ksl = 0; ksl < 2; ksl++) {
                int gk = c * 2 + ksl;
                int j0 = ksl * 16 + c2 * 2;
                uint4 ahi = *(const uint4*)(Wp + ((size_t)((0 * 4 + g) * 32 + gk) * 32 + lane) * 4);
                uint4 alo = *(const uint4*)(Wp + ((size_t)((1 * 4 + g) * 32 + gk) * 32 + lane) * 4);
#pragma unroll
                for (int nt = 0; nt < 2; nt++) {
                    int row = nt * 8 + gid;
                    unsigned bh0 = *(const unsigned*)(bufh + row * 32 + j0);
                    unsigned bh1 = *(const unsigned*)(bufh + row * 32 + j0 + 8);
                    unsigned bl0 = *(const unsigned*)(bufl + row * 32 + j0);
                    unsigned bl1 = *(const unsigned*)(bufl + row * 32 + j0 + 8);
                    MMA_BF16(acc[nt], ahi, bh0, bh1);
                    MMA_BF16(acc[nt], ahi, bl0, bl1);
                    MMA_BF16(acc[nt], alo, bh0, bh1);
                }
            }
            __syncwarp();
            if (c + 2 < NCH) issue_chunk(c + 2, bf);
        }

        // ---- gate exchange ----
#pragma unroll
        for (int nt = 0; nt < 2; nt++) {
            int bb = b0w + nt * 8 + c2 * 2;
            gBuf[(g * 16 + gid) * 64 + bb]         = acc[nt][0];
            gBuf[(g * 16 + gid) * 64 + bb + 1]     = acc[nt][1];
            gBuf[(g * 16 + gid + 8) * 64 + bb]     = acc[nt][2];
            gBuf[(g * 16 + gid + 8) * 64 + bb + 1] = acc[nt][3];
        }
        __syncthreads();   // S1: GEMM + exchange complete; wbufs free

        mbar_wait(gxmb_sh, phg);      // gxBuf ready (usually long complete)
        if (tid == 0) phg ^= 1; else phg ^= 1;   // all threads track phase

        // ---- LSTM pointwise: 2 adjacent cells per thread ----
        const float mt = mask[(size_t)t * B_ + b];
#pragma unroll
        for (int k = 0; k < 2; k++) {
            int hl = hp * 2 + k;
            float x0 = gBuf[(0 * 16 + hl) * 64 + b] + gxBuf[(0 * 16 + hl) * 64 + b] + bh[k][0];
            float x1 = gBuf[(1 * 16 + hl) * 64 + b] + gxBuf[(1 * 16 + hl) * 64 + b] + bh[k][1];
            float x2 = gBuf[(2 * 16 + hl) * 64 + b] + gxBuf[(2 * 16 + hl) * 64 + b] + bh[k][2];
            float x3 = gBuf[(3 * 16 + hl) * 64 + b] + gxBuf[(3 * 16 + hl) * 64 + b] + bh[k][3];

            float ig = 1.f / (1.f + __expf(-x0));
            float fg = 1.f / (1.f + __expf(-x1));
            float gt = tanhf(x2);
            float og = 1.f / (1.f + __expf(-x3));

            float cn = fg * creg[k] + ig * gt;
            float hv = og * tanhf(cn);
            hreg[k] = hv * mt + hreg[k] * (1.f - mt);
            creg[k] = cn * mt + creg[k] * (1.f - mt);

            if (s == T_ - 1) {
                size_t si = ((size_t)d * B_ + b) * H_ + h0 + hl;
                g_h[layer][si] = hreg[k];
                g_c[layer][si] = creg[k];
            }
        }

        // stage hn (packed u32 per j-pair) + output h into smem
#pragma unroll
        for (int gg = 0; gg < 4; gg++) {
            float v0 = hreg[0] * nz[0][gg];
            float v1 = hreg[1] * nz[1][gg];
            __nv_bfloat16 h0b = __float2bfloat16(v0);
            __nv_bfloat16 h1b = __float2bfloat16(v1);
            __nv_bfloat16 l0b = __float2bfloat16(v0 - __bfloat162float(h0b));
            __nv_bfloat16 l1b = __float2bfloat16(v1 - __bfloat162float(h1b));
            sHi32[(gg * 64 + b) * 8 + hp] =
                (unsigned)__bfloat16_as_ushort(h0b) | ((unsigned)__bfloat16_as_ushort(h1b) << 16);
            sLo32[(gg * 64 + b) * 8 + hp] =
                (unsigned)__bfloat16_as_ushort(l0b) | ((unsigned)__bfloat16_as_ushort(l1b) << 16);
        }
        sOut[b * 20 + hp * 2 + 0] = hreg[0];
        sOut[b * 20 + hp * 2 + 1] = hreg[1];
        __syncthreads();   // S2: stages complete

        // ---- cooperative coalesced hn stores (new [dg][jc][b][jw] layout) ----
        {
            unsigned* ghi = (unsigned*)hi_out;
            unsigned* glo = (unsigned*)lo_out;
#pragma unroll
            for (int i = 0; i < 4; i++) {
                int e = tid + i * 512;           // 0..2047
                int gg = e >> 9, bb = (e >> 3) & 63, p = e & 7;
                size_t gi = ((size_t)((d * 4 + gg) * 16 + jcB) * 64 + bb) * 16 + jpb + p;
                ghi[gi] = sHi32[e];
                glo[gi] = sLo32[e];
            }
        }
        __syncthreads();   // S3: hn stores issued block-wide

        if (tid == 0) {
            __threadfence();
            unsigned a = atomicAdd(&g_bar_cnt, 1u);
            if (a == (unsigned)(NBLK_S * (s + 1)) - 1u) {
                asm volatile("st.release.gpu.u32 [%0], %1;" :: "l"(&g_bar_gen), "r"((unsigned)(s + 1)) : "memory");
            } else {
                unsigned v;
                do {
                    asm volatile("ld.acquire.gpu.u32 %0, [%1];" : "=r"(v) : "l"(&g_bar_gen) : "memory");
                } while (v < (unsigned)(s + 1));
            }
        } else if (tid >= 256) {
            // output stores overlapped with tid0's barrier spin (no cross-block consumer)
            int e = tid - 256;
            int bb = e >> 2, qq = e & 3;
            float4 v = *(const float4*)&sOut[bb * 20 + qq * 4];
            *(float4*)(outp + ((size_t)t * B_ + bb) * (2 * H_) + (size_t)d * H_ + h0 + qq * 4) = v;
        }
        __syncthreads();   // S4: barrier released; safe to reuse wbufs next step
    }
}

// ---------------- finalize ----------------
__global__ void final_kernel(float* __restrict__ out) {
    int i = blockIdx.x * blockDim.x + threadIdx.x;
    if (i >= 4 * B_ * H_) return;
    int l = i >> 16;
    int r = i & 65535;
    size_t O = (size_t)T_ * B_ * 2 * H_;
    out[O + i]          = g_h[l][r];
    out[O + 131072 + i] = g_c[l][r];
}

// ---------------- launch ----------------
extern "C" void kernel_launch(void* const* d_in, const int* in_sizes, int n_in,
                              void* d_out, int out_size) {
    const float* x            = (const float*)d_in[0];
    const float* mask         = (const float*)d_in[1];
    const float* w_ih_l0      = (const float*)d_in[2];
    const float* w_hh_l0      = (const float*)d_in[3];
    const float* b_ih_l0      = (const float*)d_in[4];
    const float* b_hh_l0      = (const float*)d_in[5];
    const float* noise_in_l0  = (const float*)d_in[6];
    const float* noise_hid_l0 = (const float*)d_in[7];
    const float* w_ih_l1      = (const float*)d_in[8];
    const float* w_hh_l1      = (const float*)d_in[9];
    const float* b_ih_l1      = (const float*)d_in[10];
    const float* b_hh_l1      = (const float*)d_in[11];
    const float* noise_in_l1  = (const float*)d_in[12];
    const float* noise_hid_l1 = (const float*)d_in[13];
    float* out = (float*)d_out;

    const int SCAN_SMEM = 131072 + 65536 + 16384 + 16384 + 512;         // 229888 B
    cudaFuncSetAttribute(scan_kernel, cudaFuncAttributeMaxDynamicSharedMemorySize, SCAN_SMEM);
    const int GX_SMEM = (4 * 16 * AST + 4 * 16 * BST) * sizeof(float);  // 51200 B
    cudaFuncSetAttribute(gx_tf32_kernel, cudaFuncAttributeMaxDynamicSharedMemorySize, GX_SMEM);

    cudaStream_t sB;
    cudaStreamCreateWithFlags(&sB, cudaStreamNonBlocking);
    cudaEvent_t evA, evB, evC, evD;
    cudaEventCreateWithFlags(&evA, cudaEventDisableTiming);
    cudaEventCreateWithFlags(&evB, cudaEventDisableTiming);
    cudaEventCreateWithFlags(&evC, cudaEventDisableTiming);
    cudaEventCreateWithFlags(&evD, cudaEventDisableTiming);

    dim3 gxGrid(64, 128, 1);

    // ----- layer 0: gx on side stream, scan (flag-synced) concurrent on main -----
    init_kernel<<<512, 512>>>(0);
    cudaEventRecord(evA, 0);
    cudaStreamWaitEvent(sB, evA, 0);
    gx_tf32_kernel<<<gxGrid, 256, GX_SMEM, sB>>>(x, noise_in_l0, w_ih_l0, b_ih_l0, IN_, 0);
    cudaEventRecord(evB, sB);
    scan_kernel<<<NBLK_S, 512, SCAN_SMEM>>>(w_hh_l0, b_hh_l0, noise_hid_l0, mask, 0, out);

    // ----- layer 1 -----
    cudaStreamWaitEvent(0, evB, 0);
    init_kernel<<<512, 512>>>(1);
    cudaEventRecord(evC, 0);
    cudaStreamWaitEvent(sB, evC, 0);
    gx_tf32_kernel<<<gxGrid, 256, GX_SMEM, sB>>>(nullptr, noise_in_l1, w_ih_l1, b_ih_l1, 2 * H_, 1);
    cudaEventRecord(evD, sB);
    scan_kernel<<<NBLK_S, 512, SCAN_SMEM>>>(w_hh_l1, b_hh_l1, noise_hid_l1, mask, 1, out);

    cudaStreamWaitEvent(0, evD, 0);
    final_kernel<<<256, 512>>>(out);
}